// round 15
// baseline (speedup 1.0000x reference)
#include <cuda_runtime.h>
#include <cuda_fp16.h>
#include <cstdint>

// ===================== problem constants =====================
#define TSEG 22
#define NBT  44
#define PIX  49
#define K18  18432     // 9*2048
#define K9   9216      // 9*1024
#define K45  4608      // 9*512
#define AM   2176      // 17*128 pad of 2156

// ===================== fp32 scratch =====================
__device__ float g_mx[(size_t)NBT * 2048 * PIX];
__device__ float g_xin[2 * 2048 * PIX];
__device__ float g_y2[(size_t)NBT * 512 * PIX];
__device__ float g_mask[NBT * PIX];
__device__ float g_meanx[2 * 2048 * PIX];
__device__ float g_mxc[NBT * 2048];
__device__ float g_attfea[NBT];
__device__ float g_aw[NBT];
__device__ float g_h[2 * 512 * PIX];
__device__ float g_cst[2 * 512 * PIX];
__device__ float g_gates0[2 * 2048 * PIX];
__device__ float g_part[3300000];          // 16*200704 (merged) / conv2 partials
__device__ float g_houts[TSEG * 2 * 512];
__device__ float g_tmphc[2 * 2048 * PIX];
__device__ float g_bnc1[4 * 2048];

// ===================== split-fp16 buffers (zero-init at module load) ==========
__device__ __half g_axt_h[(size_t)AM * K18];                       // conv1 A: hi only
__device__ __half g_ay1_h[(size_t)AM * K9];                        // conv2 A: hi only
__device__ __half g_sa_h[(size_t)128 * K18],  g_sa_l[(size_t)128 * K18];
__device__ __half g_sb_h[(size_t)128 * K18],  g_sb_l[(size_t)128 * K18];
__device__ __half g_slh_h[(size_t)128 * K45], g_slh_l[(size_t)128 * K45];
__device__ __half g_wmk1_h[(size_t)1024 * K18];
__device__ __half g_wmk2_h[(size_t)512 * K9];
__device__ __half g_wgx_h[(size_t)2048 * K18];
__device__ __half g_whc1_h[(size_t)2048 * K18];
__device__ __half g_w2h_h[(size_t)512 * K9];
__device__ __half g_w2c_h[(size_t)512 * K9];
__device__ __half g_wlh_h[(size_t)2048 * K45];

// ===================== base-ISA tensor helpers (sm_80+) =====================
__device__ __forceinline__ uint32_t smem_u32(const void* p) {
    uint32_t a;
    asm("{ .reg .u64 t; cvta.to.shared.u64 t, %1; cvt.u32.u64 %0, t; }" : "=r"(a) : "l"(p));
    return a;
}
__device__ __forceinline__ void ldsm4(uint32_t* r, uint32_t addr) {
    asm volatile("ldmatrix.sync.aligned.m8n8.x4.shared.b16 {%0,%1,%2,%3}, [%4];"
        : "=r"(r[0]), "=r"(r[1]), "=r"(r[2]), "=r"(r[3]) : "r"(addr));
}
__device__ __forceinline__ void mma16816(float* d, const uint32_t* a, const uint32_t* b) {
    asm volatile(
        "mma.sync.aligned.m16n8k16.row.col.f32.f16.f16.f32 "
        "{%0,%1,%2,%3}, {%4,%5,%6,%7}, {%8,%9}, {%0,%1,%2,%3};"
        : "+f"(d[0]), "+f"(d[1]), "+f"(d[2]), "+f"(d[3])
        : "r"(a[0]), "r"(a[1]), "r"(a[2]), "r"(a[3]), "r"(b[0]), "r"(b[1]));
}
#define CP_COMMIT() asm volatile("cp.async.commit_group;" ::: "memory")

__device__ __forceinline__ void split_h(float v, __half& h, __half& l) {
    h = __float2half_rn(v);
    l = __float2half_rn(v - __half2float(h));
}

// fragment loaders for 32x32 warp tile (wm, wn in 0..3)
__device__ __forceinline__ void fragA2(uint32_t d[2][4], uint32_t sA, int k16, int wm, int lane) {
#pragma unroll
    for (int mt = 0; mt < 2; mt++) {
        uint32_t r = (uint32_t)(wm * 32 + mt * 16 + (lane & 15));
        uint32_t cby = (uint32_t)(k16 * 32 + ((lane >> 4) << 4));
        uint32_t off = r * 128 + (cby ^ ((r & 7) << 4));
        ldsm4(d[mt], sA + off);
    }
}
__device__ __forceinline__ void fragB4(uint32_t bh[4][2], uint32_t sB, int k16, int wn, int lane) {
#pragma unroll
    for (int p = 0; p < 2; p++) {
        uint32_t r = (uint32_t)(wn * 32 + p * 16 + (((lane >> 4) & 1) << 3) + (lane & 7));
        uint32_t cby = (uint32_t)(k16 * 32 + (((lane >> 3) & 1) << 4));
        uint32_t off = r * 128 + (cby ^ ((r & 7) << 4));
        uint32_t t4[4];
        ldsm4(t4, sB + off);
        bh[2 * p][0] = t4[0]; bh[2 * p][1] = t4[1];
        bh[2 * p + 1][0] = t4[2]; bh[2 * p + 1][1] = t4[3];
    }
}

// ===================== split-fp16 mma.sync GEMM =====================
// NT=2: D = Ahi @ Bhi^T (1 term), 3-stage ring.
// NT=3: D = (Ahi+Alo) @ Bhi^T (2 terms), 2-stage ring.
// Block 512 (16 warps, 4x4 layout, 32x32 per warp) -> 4 warps/SMSP for latency
// hiding. One __syncthreads per chunk: with an NSTG-stage ring the write target
// of the prefetch was last read NSTG-2 iterations ago, completed before this
// iteration's top sync.
// postop: 0 raw fp32, 1 BN+ReLU fp32, 2 BN+ReLU scattered fp16-hi im2col.
template<int NT, int NSTG>
__global__ void __launch_bounds__(512, 1) gemm_mma_k(
    const __half* Ahi, const __half* Alo, const __half* Bhi,
    float* outp, int K, int Ktile, int Mreal, int OCtot,
    const float* __restrict__ bn, int postop, long long partChunk,
    __half* __restrict__ ic_h,
    const __half* A2hi, const __half* A2lo, const __half* B2hi,
    float* out2, int zhalf)
{
    extern __shared__ char dsm[];           // NSTG stages x NT x 16KB
    __shared__ float s_sc[128], s_sh[128];
    const uint32_t STG = (uint32_t)NT * 16384u;
    const uint32_t OFF_BH = (NT == 2) ? 16384u : 32768u;

    int tid = threadIdx.x, lane = tid & 31, wid = tid >> 5;
    int wm = wid & 3, wn = wid >> 2;
    uint32_t sbase = smem_u32(dsm);

    int zz = blockIdx.z;
    if (zhalf > 0 && zz >= zhalf) {
        Ahi = A2hi; Alo = A2lo; Bhi = B2hi; outp = out2; zz -= zhalf;
    }

    int n0 = blockIdx.x * 128;
    int m0 = blockIdx.y * 128;
    long long kc0 = (long long)zz * Ktile;
    int nChunks = Ktile / 64;

    const __half* tbase[NT == 2 ? 2 : 3];
    tbase[0] = Ahi + (size_t)m0 * K + kc0;
    if (NT == 2) {
        tbase[1] = Bhi + (size_t)n0 * K + kc0;
    } else {
        tbase[1] = Alo + (size_t)m0 * K + kc0;
        tbase[2] = Bhi + (size_t)n0 * K + kc0;
    }

    auto load_chunk = [&](int c, int stg) {
        uint32_t dbase = sbase + (uint32_t)stg * STG;
#pragma unroll
        for (int j = 0; j < NT * 2; j++) {
            int tile = j >> 1;
            int within = ((j & 1) << 9) + tid;      // 0..1023
            int r = within >> 3, cs = within & 7;
            const void* g = tbase[tile] + (size_t)c * 64 + (size_t)r * K + cs * 8;
            uint32_t so = dbase + (uint32_t)tile * 16384u
                        + (uint32_t)(r * 128 + ((cs * 16) ^ ((r & 7) * 16)));
            asm volatile("cp.async.cg.shared.global [%0], [%1], 16;" :: "r"(so), "l"(g));
        }
    };

    float d[2][4][4];
#pragma unroll
    for (int a = 0; a < 2; a++)
#pragma unroll
        for (int b = 0; b < 4; b++)
#pragma unroll
            for (int c = 0; c < 4; c++) d[a][b][c] = 0.f;

    if (nChunks > 0) { load_chunk(0, 0); CP_COMMIT(); }
    if (NSTG == 3 && nChunks > 1) { load_chunk(1, 1); CP_COMMIT(); }

    for (int c = 0; c < nChunks; c++) {
        if (NSTG == 3 && c + 1 < nChunks) asm volatile("cp.async.wait_group 1;" ::: "memory");
        else                              asm volatile("cp.async.wait_group 0;" ::: "memory");
        __syncthreads();
        if (NSTG == 3) {
            if (c + 2 < nChunks) { load_chunk(c + 2, (c + 2) % 3); CP_COMMIT(); }
        } else {
            if (c + 1 < nChunks) { load_chunk(c + 1, (c + 1) & 1); CP_COMMIT(); }
        }

        int stg = c % NSTG;
        uint32_t sAh = sbase + (uint32_t)stg * STG;
        uint32_t sAl = sAh + 16384u;
        uint32_t sBh = sAh + OFF_BH;

        uint32_t ah[2][4], al[2][4], bh[4][2];
#pragma unroll
        for (int k16 = 0; k16 < 4; k16++) {
            fragA2(ah, sAh, k16, wm, lane);
            if (NT >= 3) fragA2(al, sAl, k16, wm, lane);
            fragB4(bh, sBh, k16, wn, lane);
#pragma unroll
            for (int mt = 0; mt < 2; mt++)
#pragma unroll
                for (int nt = 0; nt < 4; nt++)
                    mma16816(d[mt][nt], ah[mt], bh[nt]);
            if (NT >= 3) {
#pragma unroll
                for (int mt = 0; mt < 2; mt++)
#pragma unroll
                    for (int nt = 0; nt < 4; nt++)
                        mma16816(d[mt][nt], al[mt], bh[nt]);
            }
        }
        // no end-of-loop sync needed (see header comment)
    }
    __syncthreads();   // before smem reuse for BN params

    if (postop >= 1 && tid < 128) {
        int oc = n0 + tid;
        float g = bn[oc], b = bn[OCtot + oc], m = bn[2 * OCtot + oc], v = bn[3 * OCtot + oc];
        float sc = g * rsqrtf(v + 1e-5f);
        s_sc[tid] = sc;
        s_sh[tid] = b - m * sc;
    }
    __syncthreads();

    if (postop == 2) {
        // BN+ReLU, then scatter fp16-hi into next conv's im2col operand.
        int Kdst = OCtot * 9;
#pragma unroll
        for (int mt = 0; mt < 2; mt++) {
#pragma unroll
            for (int nt = 0; nt < 4; nt++) {
                int ln = wn * 32 + nt * 8 + 2 * (lane & 3);
                int r0 = m0 + wm * 32 + mt * 16 + (lane >> 2);
#pragma unroll
                for (int half = 0; half < 2; half++) {
                    int mrow = r0 + half * 8;
                    if (mrow < Mreal) {
                        int img = mrow / 49, p = mrow - img * 49;
                        float v0 = fmaxf(d[mt][nt][half * 2 + 0] * s_sc[ln] + s_sh[ln], 0.f);
                        float v1 = fmaxf(d[mt][nt][half * 2 + 1] * s_sc[ln + 1] + s_sh[ln + 1], 0.f);
                        __half2 hh;
                        hh.x = __float2half_rn(v0);
                        hh.y = __float2half_rn(v1);
                        int qh = p / 7, qw = p - qh * 7;
                        int oc = n0 + ln;
#pragma unroll
                        for (int kk = 0; kk < 9; kk++) {
                            int oh = qh - (kk / 3 - 1), ow = qw - (kk % 3 - 1);
                            if (oh >= 0 && oh < 7 && ow >= 0 && ow < 7) {
                                size_t o = (size_t)(img * 49 + oh * 7 + ow) * Kdst + kk * OCtot + oc;
                                *(__half2*)(ic_h + o) = hh;
                            }
                        }
                    }
                }
            }
        }
        return;
    }

    float* obase0 = outp + (size_t)zz * partChunk;
#pragma unroll
    for (int mt = 0; mt < 2; mt++) {
#pragma unroll
        for (int nt = 0; nt < 4; nt++) {
            int ln = wn * 32 + nt * 8 + 2 * (lane & 3);
            int r0 = m0 + wm * 32 + mt * 16 + (lane >> 2);
#pragma unroll
            for (int half = 0; half < 2; half++) {
                int mrow = r0 + half * 8;
                if (mrow < Mreal) {
                    int img = mrow / 49, p = mrow - img * 49;
                    float* ob = obase0 + ((size_t)img * OCtot + n0) * 49 + p;
                    float v0 = d[mt][nt][half * 2 + 0];
                    float v1 = d[mt][nt][half * 2 + 1];
                    if (postop) {
                        v0 = fmaxf(v0 * s_sc[ln] + s_sh[ln], 0.f);
                        v1 = fmaxf(v1 * s_sc[ln + 1] + s_sh[ln + 1], 0.f);
                    }
                    ob[(size_t)ln * 49] = v0;
                    ob[(size_t)(ln + 1) * 49] = v1;
                }
            }
        }
    }
}

// ===================== im2col (fp32 (img,CHtot,49) -> split fp16) =====================
__global__ void im2col_k(const float* __restrict__ in, int CHtot, int c0, int IC, int nRows,
                         __half* __restrict__ hi, __half* __restrict__ lo)
{
    int ICp = IC >> 1;
    long long idx = (long long)blockIdx.x * blockDim.x + threadIdx.x;
    long long tot = (long long)nRows * 9 * ICp;
    if (idx >= tot) return;
    int icp = (int)(idx % ICp);
    long long r2 = idx / ICp;
    int kk = (int)(r2 % 9);
    int row = (int)(r2 / 9);
    int img = row / 49, p = row - img * 49;
    int oh = p / 7, ow = p - oh * 7;
    int ih = oh + kk / 3 - 1, iw = ow + kk % 3 - 1;
    bool valid = (ih >= 0) && (ih < 7) && (iw >= 0) && (iw < 7);
    int q = valid ? (ih * 7 + iw) : 0;
    int ic = icp * 2;
    const float* base = in + ((size_t)img * CHtot + c0 + ic) * PIX + q;
    float v0 = valid ? base[0] : 0.f;
    float v1 = valid ? base[PIX] : 0.f;
    __half2 hh, ll;
    split_h(v0, hh.x, ll.x);
    split_h(v1, hh.y, ll.y);
    size_t o = (size_t)row * (IC * 9) + (size_t)kk * IC + ic;
    *(__half2*)(hi + o) = hh;
    *(__half2*)(lo + o) = ll;
}

// im2col reading x (B, 2048, T, 7, 7) directly (fused transpose); hi only
__global__ void im2colx_k(const float* __restrict__ x, __half* __restrict__ hi)
{
    const int ICp = 1024;
    long long idx = (long long)blockIdx.x * blockDim.x + threadIdx.x;
    long long tot = (long long)2156 * 9 * ICp;
    if (idx >= tot) return;
    int icp = (int)(idx % ICp);
    long long r2 = idx / ICp;
    int kk = (int)(r2 % 9);
    int row = (int)(r2 / 9);
    int img = row / 49, p = row - img * 49;
    int b = img / TSEG, t = img - b * TSEG;
    int oh = p / 7, ow = p - oh * 7;
    int ih = oh + kk / 3 - 1, iw = ow + kk % 3 - 1;
    bool valid = (ih >= 0) && (ih < 7) && (iw >= 0) && (iw < 7);
    int q = valid ? (ih * 7 + iw) : 0;
    int ic = icp * 2;
    const float* base = x + (((size_t)(b * 2048 + ic) * TSEG) + t) * PIX + q;
    float v0 = valid ? base[0] : 0.f;
    float v1 = valid ? base[(size_t)TSEG * PIX] : 0.f;
    __half2 hh;
    hh.x = __float2half_rn(v0);
    hh.y = __float2half_rn(v1);
    size_t o = (size_t)row * K18 + (size_t)kk * 2048 + ic;
    *(__half2*)(hi + o) = hh;
}

// ===================== ALL weight repacks in ONE launch =====================
__global__ void __launch_bounds__(128) repack_all_k(
    const float* s0, const float* s1, const float* s2, const float* s3,
    const float* s4, const float* s5, const float* s6, const float* s7,
    __half* d0, __half* d1, __half* d2, __half* d3,
    __half* d4, __half* d5, __half* d6, __half* d7)
{
    // job:        mk_w1  mk_w2  wgx    wlh    h0w1   c0w1   h0w2   c0w2
    const int cum[9]    = {0, 8192, 10240, 26624, 30720, 38912, 47104, 49152, 51200};
    const int OCt[8]    = {1024, 512, 2048, 2048, 1024, 1024, 512, 512};
    const int stridet[8]= {2048, 1024, 2560, 2560, 2048, 2048, 1024, 1024};
    const int c0t[8]    = {0, 0, 0, 2048, 0, 0, 0, 0};
    const int ICt[8]    = {2048, 1024, 2048, 512, 2048, 2048, 1024, 1024};

    __shared__ float s[2304];
    int bid = blockIdx.x;
    int j = 0;
    while (bid >= cum[j + 1]) j++;
    int bi = bid - cum[j];
    const float* src = (j == 0) ? s0 : (j == 1) ? s1 : (j == 2) ? s2 : (j == 3) ? s3
                     : (j == 4) ? s4 : (j == 5) ? s5 : (j == 6) ? s6 : s7;
    __half* dst = (j == 0) ? d0 : (j == 1) ? d1 : (j == 2) ? d2 : (j == 3) ? d3
                : (j == 4) ? d4 : (j == 5) ? d5 : (j == 6) ? d6 : d7;
    int OC = OCt[j], IC = ICt[j], srcStride = stridet[j], c0 = c0t[j];

    int oc = bi % OC, ic0 = (bi / OC) * 256, tid = threadIdx.x;
    const float* base = src + ((size_t)oc * srcStride + c0 + ic0) * 9;
    for (int i = tid; i < 2304; i += 128) s[i] = base[i];
    __syncthreads();
    size_t dbase = (size_t)oc * ((size_t)IC * 9) + ic0 + 2 * tid;
#pragma unroll
    for (int kk = 0; kk < 9; kk++) {
        __half2 hh;
        hh.x = __float2half_rn(s[(2 * tid) * 9 + kk]);
        hh.y = __float2half_rn(s[(2 * tid + 1) * 9 + kk]);
        *(__half2*)(dst + dbase + (size_t)kk * IC) = hh;
    }
}

__global__ void bnconcat_k(const float* __restrict__ a, const float* __restrict__ b,
                           float* __restrict__ dst)
{
    int i = blockIdx.x * blockDim.x + threadIdx.x;
    if (i >= 4 * 2048) return;
    int pr = i / 2048, j = i - pr * 2048;
    dst[i] = (j < 1024) ? a[pr * 1024 + j] : b[pr * 1024 + (j - 1024)];
}

// ===================== small kernels =====================
__global__ void finish_k(const float* __restrict__ part, int nsplit, int chunk,
                         const float* __restrict__ bn, float* __restrict__ out,
                         int OC, int total, int postop)
{
    int i = blockIdx.x * blockDim.x + threadIdx.x;
    if (i >= total) return;
    float s = 0.f;
    for (int ks = 0; ks < nsplit; ks++) s += part[(size_t)ks * chunk + i];
    if (postop == 1) {
        int oc = (i / PIX) % OC;
        float g = bn[oc], b = bn[OC + oc], m = bn[2 * OC + oc], v = bn[3 * OC + oc];
        s = (s - m) * g * rsqrtf(v + 1e-5f) + b;
        s = fmaxf(s, 0.f);
    }
    out[i] = s;
}

__global__ void mask_final_k(const float* __restrict__ y2, const float* __restrict__ w3,
                             float* __restrict__ mask, float* __restrict__ outmask)
{
    int n = blockIdx.x;
    int p = threadIdx.x, g = threadIdx.y;
    int oh = p / 7, ow = p - oh * 7;
    float s = 0.f;
    for (int ic = g; ic < 512; ic += 8) {
        const float* row = y2 + ((size_t)n * 512 + ic) * PIX;
        const float* wr = w3 + ic * 9;
#pragma unroll
        for (int kh = 0; kh < 3; kh++)
#pragma unroll
            for (int kw = 0; kw < 3; kw++) {
                int ih = oh + kh - 1, iw = ow + kw - 1;
                if (ih >= 0 && ih < 7 && iw >= 0 && iw < 7)
                    s += row[ih * 7 + iw] * wr[kh * 3 + kw];
            }
    }
    __shared__ float red[8][49];
    red[g][p] = s;
    __syncthreads();
    if (g == 0) {
        float tot = 0.f;
#pragma unroll
        for (int q = 0; q < 8; q++) tot += red[q][p];
        float m = 1.f / (1.f + expf(-tot));
        mask[n * PIX + p] = m;
        outmask[n * PIX + p] = m;
    }
}

// mx = x*mask (fused transpose) + fused per-(bt,c) spatial mean (mxc)
__global__ void mxmxc_k(const float* __restrict__ x, const float* __restrict__ mask,
                        float* __restrict__ mx, float* __restrict__ mxc)
{
    int bt = blockIdx.x;
    int c = blockIdx.y * 8 + threadIdx.y;
    int p = threadIdx.x;
    int b = bt / TSEG, t = bt - b * TSEG;
    float v = x[(((size_t)(b * 2048 + c)) * TSEG + t) * PIX + p] * mask[bt * PIX + p];
    mx[((size_t)bt * 2048 + c) * PIX + p] = v;
    __shared__ float red[8][49];
    red[threadIdx.y][p] = v;
    __syncthreads();
    if (p == 0) {
        float s = 0.f;
        for (int q = 0; q < 49; q++) s += red[threadIdx.y][q];
        mxc[bt * 2048 + c] = s * (1.f / (float)PIX);
    }
}

// fused: meanx = mean_t(mx), xin = sum_t aw[t]*mx
__global__ void meanxin_k(const float* __restrict__ mx, const float* __restrict__ aw,
                          float* __restrict__ meanx, float* __restrict__ xin)
{
    int i = blockIdx.x * blockDim.x + threadIdx.x;
    const int inner = 2048 * PIX;
    if (i >= 2 * inner) return;
    int b = i / inner, r = i - b * inner;
    float sm = 0.f, sx = 0.f;
    for (int t = 0; t < TSEG; t++) {
        float v = mx[((size_t)(b * TSEG + t)) * inner + r];
        sm += v;
        sx += aw[b * TSEG + t] * v;
    }
    meanx[i] = sm * (1.f / (float)TSEG);
    xin[i] = sx;
}

__global__ void attfea_k(const float* __restrict__ mxc, const float* __restrict__ wf,
                         float* __restrict__ attfea)
{
    int bt = blockIdx.x;
    int tid = threadIdx.x;
    __shared__ float sr[256];
    float s = 0.f;
    for (int c = tid; c < 2048; c += 256) s += mxc[bt * 2048 + c] * wf[c];
    sr[tid] = s;
    __syncthreads();
    for (int st = 128; st > 0; st >>= 1) {
        if (tid < st) sr[tid] += sr[tid + st];
        __syncthreads();
    }
    if (tid == 0) attfea[bt] = sr[0];
}

__global__ void aw_k(const float* __restrict__ attfea, float* __restrict__ aw,
                     float* __restrict__ out_aws)
{
    int b = threadIdx.x;
    if (b >= 2) return;
    float m = -1e30f;
    for (int t = 0; t < TSEG; t++) m = fmaxf(m, attfea[b * TSEG + t]);
    float sum = 0.f;
    for (int t = 0; t < TSEG; t++) sum += expf(attfea[b * TSEG + t] - m);
    for (int t = 0; t < TSEG; t++) {
        float a = expf(attfea[b * TSEG + t] - m) / sum;
        aw[b * TSEG + t] = a;
        out_aws[b * TSEG + t] = a;
    }
}

__global__ void ginit8_k(const float* __restrict__ part, const float* __restrict__ lstm_b,
                         float* __restrict__ gates0)
{
    int i = blockIdx.x * blockDim.x + threadIdx.x;
    const int total = 2 * 2048 * PIX;
    if (i >= total) return;
    int oc = (i / PIX) % 2048;
    float s = lstm_b[oc];
#pragma unroll
    for (int ks = 0; ks < 8; ks++) s += part[(size_t)ks * total + i];
    gates0[i] = s;
}

// pointwise LSTM update + spatial mean + fused split-fp16 scatter of h2 into
// next step's im2col A-operand.
__global__ void lstm_point_k(const float* __restrict__ gates0, const float* __restrict__ part,
                             float* __restrict__ h, float* __restrict__ cst,
                             float* __restrict__ houts, int t,
                             __half* __restrict__ slh_h, __half* __restrict__ slh_l)
{
    int b = blockIdx.x;
    int c = blockIdx.y * 8 + threadIdx.y;
    int p = threadIdx.x;
    size_t base = ((size_t)b * 2048) * PIX + p;
    float gi = gates0[base + (size_t)c * PIX];
    float gf = gates0[base + (size_t)(512 + c) * PIX];
    float go = gates0[base + (size_t)(1024 + c) * PIX];
    float gg = gates0[base + (size_t)(1536 + c) * PIX];
#pragma unroll
    for (int ks = 0; ks < 8; ks++) {
        size_t pb = ((size_t)(ks * 2 + b) * 2048) * PIX + p;
        gi += part[pb + (size_t)c * PIX];
        gf += part[pb + (size_t)(512 + c) * PIX];
        go += part[pb + (size_t)(1024 + c) * PIX];
        gg += part[pb + (size_t)(1536 + c) * PIX];
    }
    size_t hidx = ((size_t)b * 512 + c) * PIX + p;
    float cprev = cst[hidx];
    float si = 1.f / (1.f + expf(-gi));
    float sf = 1.f / (1.f + expf(-gf));
    float so = 1.f / (1.f + expf(-go));
    float c2 = sf * cprev + si * tanhf(gg);
    float h2 = so * tanhf(c2);
    cst[hidx] = c2;
    h[hidx] = h2;

    {
        __half hh, ll;
        split_h(h2, hh, ll);
        int qh = p / 7, qw = p - qh * 7;
#pragma unroll
        for (int kk = 0; kk < 9; kk++) {
            int oh = qh - (kk / 3 - 1), ow = qw - (kk % 3 - 1);
            if (oh >= 0 && oh < 7 && ow >= 0 && ow < 7) {
                size_t o = (size_t)(b * 49 + oh * 7 + ow) * K45 + kk * 512 + c;
                slh_h[o] = hh;
                slh_l[o] = ll;
            }
        }
    }

    __shared__ float red[8][49];
    red[threadIdx.y][p] = h2;
    __syncthreads();
    if (p == 0) {
        float s = 0.f;
        for (int q = 0; q < 49; q++) s += red[threadIdx.y][q];
        houts[((size_t)t * 2 + b) * 512 + c] = s * (1.f / (float)PIX);
    }
}

__global__ void final_k(const float* __restrict__ houts, const float* __restrict__ fc_w,
                        const float* __restrict__ fc_b, float* __restrict__ out)
{
    __shared__ float om[1024];
    int tid = threadIdx.x;
    for (int i = tid; i < 1024; i += 512) {
        int b = i / 512, c = i - b * 512;
        float s = 0.f;
        for (int t = 0; t < TSEG; t++) s += houts[((size_t)t * 2 + b) * 512 + c];
        om[i] = s * (1.f / (float)TSEG);
    }
    __syncthreads();
    for (int i = tid; i < 202; i += 512) {
        int b = i / 101, k = i - b * 101;
        float s = fc_b[k];
        for (int c = 0; c < 512; c++) s += om[b * 512 + c] * fc_w[k * 512 + c];
        out[i] = s;
    }
    if (tid == 0) { out[2402] = 0.f; out[2403] = 0.f; }
}

// ===================== host =====================
static float* symaddr(const void* sym) { void* p = nullptr; cudaGetSymbolAddress(&p, sym); return (float*)p; }
static __half* symaddrh(const void* sym) { void* p = nullptr; cudaGetSymbolAddress(&p, sym); return (__half*)p; }

#define GEMM_SMEM2 (3 * 32768)   // NT=2, 3-stage
#define GEMM_SMEM3 (2 * 49152)   // NT=3, 2-stage

extern "C" void kernel_launch(void* const* d_in, const int* in_sizes, int n_in,
                              void* d_out, int out_size)
{
    const float* x      = (const float*)d_in[0];
    const float* wf     = (const float*)d_in[1];
    const float* fc_w   = (const float*)d_in[3];
    const float* fc_b   = (const float*)d_in[4];
    const float* h0_w1  = (const float*)d_in[5];
    const float* h0_bn1 = (const float*)d_in[6];
    const float* h0_w2  = (const float*)d_in[7];
    const float* h0_bn2 = (const float*)d_in[8];
    const float* c0_w1  = (const float*)d_in[9];
    const float* c0_bn1 = (const float*)d_in[10];
    const float* c0_w2  = (const float*)d_in[11];
    const float* c0_bn2 = (const float*)d_in[12];
    const float* mk_w1  = (const float*)d_in[13];
    const float* mk_bn1 = (const float*)d_in[14];
    const float* mk_w2  = (const float*)d_in[15];
    const float* mk_bn2 = (const float*)d_in[16];
    const float* mk_w3  = (const float*)d_in[17];
    const float* lstm_w = (const float*)d_in[18];
    const float* lstm_b = (const float*)d_in[19];
    float* out = (float*)d_out;

    cudaFuncSetAttribute((const void*)gemm_mma_k<2,3>, cudaFuncAttributeMaxDynamicSharedMemorySize, GEMM_SMEM2);
    cudaFuncSetAttribute((const void*)gemm_mma_k<3,2>, cudaFuncAttributeMaxDynamicSharedMemorySize, GEMM_SMEM3);

    float *mx = symaddr(g_mx), *xin = symaddr(g_xin);
    float *y2 = symaddr(g_y2), *mask = symaddr(g_mask);
    float *meanx = symaddr(g_meanx), *mxc = symaddr(g_mxc), *attfea = symaddr(g_attfea);
    float *aw = symaddr(g_aw), *h = symaddr(g_h), *cst = symaddr(g_cst);
    float *gates0 = symaddr(g_gates0), *part = symaddr(g_part), *houts = symaddr(g_houts);
    float *tmphc = symaddr(g_tmphc), *bnc1 = symaddr(g_bnc1);

    __half *axt_h = symaddrh(g_axt_h);
    __half *ay1_h = symaddrh(g_ay1_h);
    __half *sa_h = symaddrh(g_sa_h),   *sa_l = symaddrh(g_sa_l);
    __half *sb_h = symaddrh(g_sb_h),   *sb_l = symaddrh(g_sb_l);
    __half *slh_h = symaddrh(g_slh_h), *slh_l = symaddrh(g_slh_l);
    __half *wmk1_h = symaddrh(g_wmk1_h);
    __half *wmk2_h = symaddrh(g_wmk2_h);
    __half *wgx_h = symaddrh(g_wgx_h);
    __half *whc1_h = symaddrh(g_whc1_h);
    __half *w2h_h = symaddrh(g_w2h_h);
    __half *w2c_h = symaddrh(g_w2c_h);
    __half *wlh_h = symaddrh(g_wlh_h);

    auto blk = [](long long n) { return (unsigned)((n + 255) / 256); };
    dim3 cb(49, 8);
    const long long GCH = 2 * 2048 * PIX;   // 200704, gate partial chunk
    const long long HCH = 2 * 512 * PIX;    // 50176

    // ---- ALL weight repacks in one launch (hi only) ----
    repack_all_k<<<51200, 128>>>(mk_w1, mk_w2, lstm_w, lstm_w, h0_w1, c0_w1, h0_w2, c0_w2,
                                 wmk1_h, wmk2_h, wgx_h, wlh_h,
                                 whc1_h, whc1_h + (size_t)1024 * K18, w2h_h, w2c_h);
    bnconcat_k<<<32, 256>>>(h0_bn1, c0_bn1, bnc1);

    // ---- mask path: conv1 1-term; epilogue scatters fp16-hi im2col for conv2 (1-term) ----
    im2colx_k<<<blk((long long)2156 * 9 * 1024), 256>>>(x, axt_h);
    {
        dim3 grid(8, 17, 1);
        gemm_mma_k<2,3><<<grid, 512, GEMM_SMEM2>>>(axt_h, nullptr, wmk1_h, part, K18, K18, 2156, 1024,
                                                   mk_bn1, 2, 0, ay1_h,
                                                   nullptr, nullptr, nullptr, nullptr, 0);
    }
    {
        dim3 grid(4, 17, 2);
        gemm_mma_k<2,3><<<grid, 512, GEMM_SMEM2>>>(ay1_h, nullptr, wmk2_h, part, K9, K9 / 2, 2156, 512,
                                                   nullptr, 0, (long long)44 * 512 * PIX, nullptr,
                                                   nullptr, nullptr, nullptr, nullptr, 0);
    }
    finish_k<<<blk((long long)44 * 512 * PIX), 256>>>(part, 2, 44 * 512 * PIX, mk_bn2, y2,
                                                      512, 44 * 512 * PIX, 1);
    mask_final_k<<<NBT, cb>>>(y2, mk_w3, mask, out + 246);

    // ---- masked features + attention ----
    mxmxc_k<<<dim3(NBT, 256), cb>>>(x, mask, mx, mxc);
    attfea_k<<<NBT, 256>>>(mxc, wf, attfea);
    aw_k<<<1, 32>>>(attfea, aw, out + 202);
    meanxin_k<<<blk(2 * 2048 * PIX), 256>>>(mx, aw, meanx, xin);

    // ---- xin GEMM + hc1 GEMM merged into ONE launch (z-multiplex) ----
    im2col_k<<<blk((long long)98 * 9 * 1024), 256>>>(xin, 2048, 0, 2048, 98, sa_h, sa_l);
    im2col_k<<<blk((long long)98 * 9 * 1024), 256>>>(meanx, 2048, 0, 2048, 98, sb_h, sb_l);
    {
        dim3 grid(16, 1, 16);   // z 0..7 xin->wgx->part[0..8); z 8..15 meanx->whc1->part[8..16)
        gemm_mma_k<3,2><<<grid, 512, GEMM_SMEM3>>>(sa_h, sa_l, wgx_h, part, K18, K18 / 8, 98, 2048,
                                                   nullptr, 0, GCH, nullptr,
                                                   sb_h, sb_l, whc1_h, part + 8 * GCH, 8);
    }
    ginit8_k<<<blk(GCH), 256>>>(part, lstm_b, gates0);
    finish_k<<<blk(GCH), 256>>>(part + 8 * GCH, 8, (int)GCH, bnc1, tmphc, 2048, (int)GCH, 1);

    // ---- hc2: both branches in ONE launch ----
    im2col_k<<<blk((long long)98 * 9 * 512), 256>>>(tmphc, 2048, 0, 1024, 98, sa_h, sa_l);
    im2col_k<<<blk((long long)98 * 9 * 512), 256>>>(tmphc, 2048, 1024, 1024, 98, sb_h, sb_l);
    {
        dim3 grid(4, 1, 8);     // z 0..3 h-branch; z 4..7 c-branch
        gemm_mma_k<3,2><<<grid, 512, GEMM_SMEM3>>>(sa_h, sa_l, w2h_h, part, K9, K9 / 4, 98, 512,
                                                   nullptr, 0, HCH, nullptr,
                                                   sb_h, sb_l, w2c_h, part + 4 * HCH, 4);
    }
    finish_k<<<blk(HCH), 256>>>(part, 4, (int)HCH, h0_bn2, h, 512, (int)HCH, 1);
    finish_k<<<blk(HCH), 256>>>(part + 4 * HCH, 4, (int)HCH, c0_bn2, cst, 512, (int)HCH, 1);

    // ---- seed im2col for h0, then recurrence (2-term: A=h split, B=wlh hi) ----
    im2col_k<<<blk((long long)98 * 9 * 256), 256>>>(h, 512, 0, 512, 98, slh_h, slh_l);
    for (int t = 0; t < TSEG; t++) {
        dim3 grid(16, 1, 8);
        gemm_mma_k<3,2><<<grid, 512, GEMM_SMEM3>>>(slh_h, slh_l, wlh_h, part, K45, K45 / 8, 98, 2048,
                                                   nullptr, 0, GCH, nullptr,
                                                   nullptr, nullptr, nullptr, nullptr, 0);
        lstm_point_k<<<dim3(2, 64), cb>>>(gates0, part, h, cst, houts, t, slh_h, slh_l);
    }

    final_k<<<1, 512>>>(houts, fc_w, fc_b, out);
}

// round 16
// speedup vs baseline: 1.0165x; 1.0165x over previous
#include <cuda_runtime.h>
#include <cuda_fp16.h>
#include <cstdint>

// ===================== problem constants =====================
#define TSEG 22
#define NBT  44
#define PIX  49
#define K18  18432     // 9*2048
#define K9   9216      // 9*1024
#define K45  4608      // 9*512
#define AM   2176      // 17*128 pad of 2156

// ===================== fp32 scratch =====================
__device__ float g_mx[(size_t)NBT * 2048 * PIX];
__device__ float g_xin[2 * 2048 * PIX];
__device__ float g_y2[(size_t)NBT * 512 * PIX];
__device__ float g_mask[NBT * PIX];
__device__ float g_meanx[2 * 2048 * PIX];
__device__ float g_mxc[NBT * 2048];
__device__ float g_attfea[NBT];
__device__ float g_aw[NBT];
__device__ float g_h[2 * 512 * PIX];
__device__ float g_cst[2 * 512 * PIX];
__device__ float g_gates0[2 * 2048 * PIX];
__device__ float g_part[3300000];
__device__ float g_houts[TSEG * 2 * 512];
__device__ float g_tmphc[2 * 2048 * PIX];
__device__ float g_bnc1[4 * 2048];
__device__ unsigned g_gbar;

// ===================== split-fp16 buffers (zero-init at module load) ==========
__device__ __half g_axt_h[(size_t)AM * K18];
__device__ __half g_ay1_h[(size_t)AM * K9];
__device__ __half g_sa_h[(size_t)128 * K18],  g_sa_l[(size_t)128 * K18];
__device__ __half g_sb_h[(size_t)128 * K18],  g_sb_l[(size_t)128 * K18];
__device__ __half g_slh_h[(size_t)128 * K45], g_slh_l[(size_t)128 * K45];
__device__ __half g_wmk1_h[(size_t)1024 * K18];
__device__ __half g_wmk2_h[(size_t)512 * K9];
__device__ __half g_wgx_h[(size_t)2048 * K18];
__device__ __half g_whc1_h[(size_t)2048 * K18];
__device__ __half g_w2h_h[(size_t)512 * K9];
__device__ __half g_w2c_h[(size_t)512 * K9];
__device__ __half g_wlh_h[(size_t)2048 * K45];

// ===================== base-ISA tensor helpers (sm_80+) =====================
__device__ __forceinline__ uint32_t smem_u32(const void* p) {
    uint32_t a;
    asm("{ .reg .u64 t; cvta.to.shared.u64 t, %1; cvt.u32.u64 %0, t; }" : "=r"(a) : "l"(p));
    return a;
}
__device__ __forceinline__ void ldsm4(uint32_t* r, uint32_t addr) {
    asm volatile("ldmatrix.sync.aligned.m8n8.x4.shared.b16 {%0,%1,%2,%3}, [%4];"
        : "=r"(r[0]), "=r"(r[1]), "=r"(r[2]), "=r"(r[3]) : "r"(addr));
}
__device__ __forceinline__ void mma16816(float* d, const uint32_t* a, const uint32_t* b) {
    asm volatile(
        "mma.sync.aligned.m16n8k16.row.col.f32.f16.f16.f32 "
        "{%0,%1,%2,%3}, {%4,%5,%6,%7}, {%8,%9}, {%0,%1,%2,%3};"
        : "+f"(d[0]), "+f"(d[1]), "+f"(d[2]), "+f"(d[3])
        : "r"(a[0]), "r"(a[1]), "r"(a[2]), "r"(a[3]), "r"(b[0]), "r"(b[1]));
}
#define CP_COMMIT() asm volatile("cp.async.commit_group;" ::: "memory")

__device__ __forceinline__ void split_h(float v, __half& h, __half& l) {
    h = __float2half_rn(v);
    l = __float2half_rn(v - __half2float(h));
}

// ===================== split-fp16 mma.sync GEMM (round-13 config) =====================
// NT=2: D = Ahi @ Bhi^T (1 term).  NT=3: D = (Ahi+Alo) @ Bhi^T (2 terms).
// grid (N/128, ceil(M/128), z), block 256 (8 warps, 2x4 -> 64x32/warp), 3-stage ring.
// postop: 0 raw fp32, 1 BN+ReLU fp32, 2 BN+ReLU scattered fp16-hi im2col.
template<int NT>
__global__ void __launch_bounds__(256, 1) gemm_mma_k(
    const __half* Ahi, const __half* Alo, const __half* Bhi,
    float* outp, int K, int Ktile, int Mreal, int OCtot,
    const float* __restrict__ bn, int postop, long long partChunk,
    __half* __restrict__ ic_h,
    const __half* A2hi, const __half* A2lo, const __half* B2hi,
    float* out2, int zhalf)
{
    extern __shared__ char dsm[];
    __shared__ float s_sc[128], s_sh[128];
    const uint32_t STG = (uint32_t)NT * 16384u;
    const uint32_t OFF_BH = (NT == 2) ? 16384u : 32768u;

    int tid = threadIdx.x, lane = tid & 31, wid = tid >> 5;
    int wm = wid & 1, wn = wid >> 1;
    uint32_t sbase = smem_u32(dsm);

    int zz = blockIdx.z;
    if (zhalf > 0 && zz >= zhalf) {
        Ahi = A2hi; Alo = A2lo; Bhi = B2hi; outp = out2; zz -= zhalf;
    }

    int n0 = blockIdx.x * 128;
    int m0 = blockIdx.y * 128;
    long long kc0 = (long long)zz * Ktile;
    int nChunks = Ktile / 64;

    const __half* tbase[NT == 2 ? 2 : 3];
    tbase[0] = Ahi + (size_t)m0 * K + kc0;
    if (NT == 2) {
        tbase[1] = Bhi + (size_t)n0 * K + kc0;
    } else {
        tbase[1] = Alo + (size_t)m0 * K + kc0;
        tbase[2] = Bhi + (size_t)n0 * K + kc0;
    }

    auto load_chunk = [&](int c, int stg) {
        uint32_t dbase = sbase + (uint32_t)stg * STG;
#pragma unroll
        for (int j = 0; j < NT * 4; j++) {
            int tile = j >> 2;
            int within = ((j & 3) << 8) + tid;
            int r = within >> 3, cs = within & 7;
            const void* g = tbase[tile] + (size_t)c * 64 + (size_t)r * K + cs * 8;
            uint32_t so = dbase + (uint32_t)tile * 16384u
                        + (uint32_t)(r * 128 + ((cs * 16) ^ ((r & 7) * 16)));
            asm volatile("cp.async.cg.shared.global [%0], [%1], 16;" :: "r"(so), "l"(g));
        }
    };

    float d[4][4][4];
#pragma unroll
    for (int a = 0; a < 4; a++)
#pragma unroll
        for (int b = 0; b < 4; b++)
#pragma unroll
            for (int c = 0; c < 4; c++) d[a][b][c] = 0.f;

    if (nChunks > 0) { load_chunk(0, 0); CP_COMMIT(); }
    if (nChunks > 1) { load_chunk(1, 1); CP_COMMIT(); }

    for (int c = 0; c < nChunks; c++) {
        if (c + 1 < nChunks) asm volatile("cp.async.wait_group 1;" ::: "memory");
        else                 asm volatile("cp.async.wait_group 0;" ::: "memory");
        __syncthreads();
        if (c + 2 < nChunks) { load_chunk(c + 2, (c + 2) % 3); CP_COMMIT(); }

        int stg = c % 3;
        uint32_t sAh = sbase + (uint32_t)stg * STG;
        uint32_t sAl = sAh + 16384u;
        uint32_t sBh = sAh + OFF_BH;

#pragma unroll
        for (int k16 = 0; k16 < 4; k16++) {
            uint32_t ah[4][4], al[4][4], bh[4][2];
#pragma unroll
            for (int mt = 0; mt < 4; mt++) {
                uint32_t r = (uint32_t)(wm * 64 + mt * 16 + (lane & 15));
                uint32_t cby = (uint32_t)(k16 * 32 + ((lane >> 4) << 4));
                uint32_t off = r * 128 + (cby ^ ((r & 7) << 4));
                ldsm4(ah[mt], sAh + off);
                if (NT >= 3) ldsm4(al[mt], sAl + off);
            }
#pragma unroll
            for (int p = 0; p < 2; p++) {
                uint32_t r = (uint32_t)(wn * 32 + p * 16 + (((lane >> 4) & 1) << 3) + (lane & 7));
                uint32_t cby = (uint32_t)(k16 * 32 + (((lane >> 3) & 1) << 4));
                uint32_t off = r * 128 + (cby ^ ((r & 7) << 4));
                uint32_t t4[4];
                ldsm4(t4, sBh + off);
                bh[2 * p][0] = t4[0]; bh[2 * p][1] = t4[1];
                bh[2 * p + 1][0] = t4[2]; bh[2 * p + 1][1] = t4[3];
            }
#pragma unroll
            for (int mt = 0; mt < 4; mt++)
#pragma unroll
                for (int nt = 0; nt < 4; nt++) {
                    mma16816(d[mt][nt], ah[mt], bh[nt]);
                    if (NT >= 3) mma16816(d[mt][nt], al[mt], bh[nt]);
                }
        }
        __syncthreads();
    }

    if (postop >= 1 && tid < 128) {
        int oc = n0 + tid;
        float g = bn[oc], b = bn[OCtot + oc], m = bn[2 * OCtot + oc], v = bn[3 * OCtot + oc];
        float sc = g * rsqrtf(v + 1e-5f);
        s_sc[tid] = sc;
        s_sh[tid] = b - m * sc;
    }
    __syncthreads();

    if (postop == 2) {
        int Kdst = OCtot * 9;
#pragma unroll
        for (int mt = 0; mt < 4; mt++) {
#pragma unroll
            for (int nt = 0; nt < 4; nt++) {
                int ln = wn * 32 + nt * 8 + 2 * (lane & 3);
                int r0 = m0 + wm * 64 + mt * 16 + (lane >> 2);
#pragma unroll
                for (int half = 0; half < 2; half++) {
                    int mrow = r0 + half * 8;
                    if (mrow < Mreal) {
                        int img = mrow / 49, p = mrow - img * 49;
                        float v0 = fmaxf(d[mt][nt][half * 2 + 0] * s_sc[ln] + s_sh[ln], 0.f);
                        float v1 = fmaxf(d[mt][nt][half * 2 + 1] * s_sc[ln + 1] + s_sh[ln + 1], 0.f);
                        __half2 hh;
                        hh.x = __float2half_rn(v0);
                        hh.y = __float2half_rn(v1);
                        int qh = p / 7, qw = p - qh * 7;
                        int oc = n0 + ln;
#pragma unroll
                        for (int kk = 0; kk < 9; kk++) {
                            int oh = qh - (kk / 3 - 1), ow = qw - (kk % 3 - 1);
                            if (oh >= 0 && oh < 7 && ow >= 0 && ow < 7) {
                                size_t o = (size_t)(img * 49 + oh * 7 + ow) * Kdst + kk * OCtot + oc;
                                *(__half2*)(ic_h + o) = hh;
                            }
                        }
                    }
                }
            }
        }
        return;
    }

    float* obase0 = outp + (size_t)zz * partChunk;
#pragma unroll
    for (int mt = 0; mt < 4; mt++) {
#pragma unroll
        for (int nt = 0; nt < 4; nt++) {
            int ln = wn * 32 + nt * 8 + 2 * (lane & 3);
            int r0 = m0 + wm * 64 + mt * 16 + (lane >> 2);
#pragma unroll
            for (int half = 0; half < 2; half++) {
                int mrow = r0 + half * 8;
                if (mrow < Mreal) {
                    int img = mrow / 49, p = mrow - img * 49;
                    float* ob = obase0 + ((size_t)img * OCtot + n0) * 49 + p;
                    float v0 = d[mt][nt][half * 2 + 0];
                    float v1 = d[mt][nt][half * 2 + 1];
                    if (postop) {
                        v0 = fmaxf(v0 * s_sc[ln] + s_sh[ln], 0.f);
                        v1 = fmaxf(v1 * s_sc[ln + 1] + s_sh[ln + 1], 0.f);
                    }
                    ob[(size_t)ln * 49] = v0;
                    ob[(size_t)(ln + 1) * 49] = v1;
                }
            }
        }
    }
}

// ===================== PERSISTENT fused recurrence =====================
// grid 128 (16 n-tiles x 8 k-splits), block 256, 144KB smem -> 1 CTA/SM,
// 128 <= 148 SMs: all CTAs co-resident, software global barrier is safe.
// Per step: phase A = 2-term GEMM partial (identical math to gemm_mma_k<3>),
// global barrier, phase B = LSTM pointwise (cell state in registers, partials
// read via __ldcg to bypass stale L1; scatter read next step via cp.async.cg),
// global barrier.
__global__ void zerobar_k() { g_gbar = 0u; }

__device__ __forceinline__ void global_bar(unsigned target) {
    __syncthreads();
    if (threadIdx.x == 0) {
        __threadfence();
        atomicAdd(&g_gbar, 1u);
        while (atomicAdd(&g_gbar, 0u) < target) { }
    }
    __syncthreads();
}

__global__ void __launch_bounds__(256, 1) lstm_loop_k(
    __half* __restrict__ slh_h, __half* __restrict__ slh_l,
    const __half* __restrict__ wlh,
    float* __restrict__ part, const float* __restrict__ gates0,
    const float* __restrict__ cst0, float* __restrict__ houts)
{
    extern __shared__ char dsm[];            // 3 stages x 3 tiles x 16KB
    int tid = threadIdx.x, lane = tid & 31, wid = tid >> 5;
    int wm = wid & 1, wn = wid >> 1;
    uint32_t sbase = smem_u32(dsm);

    int ntile = blockIdx.x & 15, ks = blockIdx.x >> 4;
    int n0 = ntile * 128;
    long long kc0 = (long long)ks * 576;     // Ktile = 4608/8
    const long long GCH = 2LL * 2048 * PIX;

    // phase-B persistent state: warp owns (b,c) pair; cell state in registers
    int pairi = blockIdx.x * 8 + wid;        // 0..1023
    int pb = pairi >> 9, pc = pairi & 511;
    float cstate[2];
    {
        size_t hb = ((size_t)pb * 512 + pc) * PIX;
        cstate[0] = cst0[hb + lane % 49];            // lane<49 valid; others unused
        cstate[1] = (lane + 32 < 49) ? cst0[hb + lane + 32] : 0.f;
        if (lane >= 49) cstate[0] = 0.f;
        else cstate[0] = cst0[hb + lane];
    }

    unsigned barcnt = 0;

    for (int t = 0; t < TSEG; t++) {
        // ================= phase A: GEMM partial =================
        const __half* tb0 = slh_h + kc0;                      // m0 = 0
        const __half* tb1 = slh_l + kc0;
        const __half* tb2 = wlh + (size_t)n0 * K45 + kc0;

        auto load_chunk = [&](int c, int stg) {
            uint32_t dbase = sbase + (uint32_t)stg * 49152u;
#pragma unroll
            for (int j = 0; j < 12; j++) {
                int tile = j >> 2;
                int within = ((j & 3) << 8) + tid;
                int r = within >> 3, cs = within & 7;
                const __half* tb = (tile == 0) ? tb0 : (tile == 1) ? tb1 : tb2;
                const void* g = tb + (size_t)c * 64 + (size_t)r * K45 + cs * 8;
                uint32_t so = dbase + (uint32_t)tile * 16384u
                            + (uint32_t)(r * 128 + ((cs * 16) ^ ((r & 7) * 16)));
                asm volatile("cp.async.cg.shared.global [%0], [%1], 16;" :: "r"(so), "l"(g));
            }
        };

        float d[4][4][4];
#pragma unroll
        for (int a = 0; a < 4; a++)
#pragma unroll
            for (int b = 0; b < 4; b++)
#pragma unroll
                for (int c = 0; c < 4; c++) d[a][b][c] = 0.f;

        load_chunk(0, 0); CP_COMMIT();
        load_chunk(1, 1); CP_COMMIT();

        for (int c = 0; c < 9; c++) {
            if (c + 1 < 9) asm volatile("cp.async.wait_group 1;" ::: "memory");
            else           asm volatile("cp.async.wait_group 0;" ::: "memory");
            __syncthreads();
            if (c + 2 < 9) { load_chunk(c + 2, (c + 2) % 3); CP_COMMIT(); }

            int stg = c % 3;
            uint32_t sAh = sbase + (uint32_t)stg * 49152u;
            uint32_t sAl = sAh + 16384u;
            uint32_t sBh = sAh + 32768u;

#pragma unroll
            for (int k16 = 0; k16 < 4; k16++) {
                uint32_t ah[4][4], al[4][4], bh[4][2];
#pragma unroll
                for (int mt = 0; mt < 4; mt++) {
                    uint32_t r = (uint32_t)(wm * 64 + mt * 16 + (lane & 15));
                    uint32_t cby = (uint32_t)(k16 * 32 + ((lane >> 4) << 4));
                    uint32_t off = r * 128 + (cby ^ ((r & 7) << 4));
                    ldsm4(ah[mt], sAh + off);
                    ldsm4(al[mt], sAl + off);
                }
#pragma unroll
                for (int p = 0; p < 2; p++) {
                    uint32_t r = (uint32_t)(wn * 32 + p * 16 + (((lane >> 4) & 1) << 3) + (lane & 7));
                    uint32_t cby = (uint32_t)(k16 * 32 + (((lane >> 3) & 1) << 4));
                    uint32_t off = r * 128 + (cby ^ ((r & 7) << 4));
                    uint32_t t4[4];
                    ldsm4(t4, sBh + off);
                    bh[2 * p][0] = t4[0]; bh[2 * p][1] = t4[1];
                    bh[2 * p + 1][0] = t4[2]; bh[2 * p + 1][1] = t4[3];
                }
#pragma unroll
                for (int mt = 0; mt < 4; mt++)
#pragma unroll
                    for (int nt = 0; nt < 4; nt++) {
                        mma16816(d[mt][nt], ah[mt], bh[nt]);
                        mma16816(d[mt][nt], al[mt], bh[nt]);
                    }
            }
            __syncthreads();
        }

        // write raw fp32 partial
        float* obase0 = part + (size_t)ks * GCH;
#pragma unroll
        for (int mt = 0; mt < 4; mt++) {
#pragma unroll
            for (int nt = 0; nt < 4; nt++) {
                int ln = wn * 32 + nt * 8 + 2 * (lane & 3);
                int r0 = wm * 64 + mt * 16 + (lane >> 2);
#pragma unroll
                for (int half = 0; half < 2; half++) {
                    int mrow = r0 + half * 8;
                    if (mrow < 98) {
                        int img = mrow / 49, p = mrow - img * 49;
                        float* ob = obase0 + ((size_t)img * 2048 + n0) * 49 + p;
                        ob[(size_t)ln * 49] = d[mt][nt][half * 2 + 0];
                        ob[(size_t)(ln + 1) * 49] = d[mt][nt][half * 2 + 1];
                    }
                }
            }
        }

        barcnt++; global_bar(barcnt * 128u);

        // ================= phase B: LSTM pointwise =================
        float hs[2];
#pragma unroll
        for (int s = 0; s < 2; s++) {
            int p = lane + 32 * s;
            float h2v = 0.f;
            if (p < 49) {
                size_t base = ((size_t)pb * 2048) * PIX + p;
                float gi = gates0[base + (size_t)pc * PIX];
                float gf = gates0[base + (size_t)(512 + pc) * PIX];
                float go = gates0[base + (size_t)(1024 + pc) * PIX];
                float gg = gates0[base + (size_t)(1536 + pc) * PIX];
#pragma unroll
                for (int k2 = 0; k2 < 8; k2++) {
                    size_t pbs = ((size_t)(k2 * 2 + pb) * 2048) * PIX + p;
                    gi += __ldcg(part + pbs + (size_t)pc * PIX);
                    gf += __ldcg(part + pbs + (size_t)(512 + pc) * PIX);
                    go += __ldcg(part + pbs + (size_t)(1024 + pc) * PIX);
                    gg += __ldcg(part + pbs + (size_t)(1536 + pc) * PIX);
                }
                float si = 1.f / (1.f + expf(-gi));
                float sf = 1.f / (1.f + expf(-gf));
                float so = 1.f / (1.f + expf(-go));
                float c2 = sf * cstate[s] + si * tanhf(gg);
                h2v = so * tanhf(c2);
                cstate[s] = c2;
                __half hh, ll;
                split_h(h2v, hh, ll);
                int qh = p / 7, qw = p - qh * 7;
#pragma unroll
                for (int kk = 0; kk < 9; kk++) {
                    int oh = qh - (kk / 3 - 1), ow = qw - (kk % 3 - 1);
                    if (oh >= 0 && oh < 7 && ow >= 0 && ow < 7) {
                        size_t o = (size_t)(pb * 49 + oh * 7 + ow) * K45 + kk * 512 + pc;
                        slh_h[o] = hh;
                        slh_l[o] = ll;
                    }
                }
            }
            float r = h2v;
#pragma unroll
            for (int off = 16; off > 0; off >>= 1)
                r += __shfl_down_sync(0xffffffffu, r, off);
            hs[s] = r;
        }
        if (lane == 0)
            houts[((size_t)t * 2 + pb) * 512 + pc] = (hs[0] + hs[1]) * (1.f / (float)PIX);

        barcnt++; global_bar(barcnt * 128u);
    }
}

// ===================== im2col (fp32 (img,CHtot,49) -> split fp16) =====================
__global__ void im2col_k(const float* __restrict__ in, int CHtot, int c0, int IC, int nRows,
                         __half* __restrict__ hi, __half* __restrict__ lo)
{
    int ICp = IC >> 1;
    long long idx = (long long)blockIdx.x * blockDim.x + threadIdx.x;
    long long tot = (long long)nRows * 9 * ICp;
    if (idx >= tot) return;
    int icp = (int)(idx % ICp);
    long long r2 = idx / ICp;
    int kk = (int)(r2 % 9);
    int row = (int)(r2 / 9);
    int img = row / 49, p = row - img * 49;
    int oh = p / 7, ow = p - oh * 7;
    int ih = oh + kk / 3 - 1, iw = ow + kk % 3 - 1;
    bool valid = (ih >= 0) && (ih < 7) && (iw >= 0) && (iw < 7);
    int q = valid ? (ih * 7 + iw) : 0;
    int ic = icp * 2;
    const float* base = in + ((size_t)img * CHtot + c0 + ic) * PIX + q;
    float v0 = valid ? base[0] : 0.f;
    float v1 = valid ? base[PIX] : 0.f;
    __half2 hh, ll;
    split_h(v0, hh.x, ll.x);
    split_h(v1, hh.y, ll.y);
    size_t o = (size_t)row * (IC * 9) + (size_t)kk * IC + ic;
    *(__half2*)(hi + o) = hh;
    *(__half2*)(lo + o) = ll;
}

// im2col reading x (B, 2048, T, 7, 7) directly (fused transpose); hi only
__global__ void im2colx_k(const float* __restrict__ x, __half* __restrict__ hi)
{
    const int ICp = 1024;
    long long idx = (long long)blockIdx.x * blockDim.x + threadIdx.x;
    long long tot = (long long)2156 * 9 * ICp;
    if (idx >= tot) return;
    int icp = (int)(idx % ICp);
    long long r2 = idx / ICp;
    int kk = (int)(r2 % 9);
    int row = (int)(r2 / 9);
    int img = row / 49, p = row - img * 49;
    int b = img / TSEG, t = img - b * TSEG;
    int oh = p / 7, ow = p - oh * 7;
    int ih = oh + kk / 3 - 1, iw = ow + kk % 3 - 1;
    bool valid = (ih >= 0) && (ih < 7) && (iw >= 0) && (iw < 7);
    int q = valid ? (ih * 7 + iw) : 0;
    int ic = icp * 2;
    const float* base = x + (((size_t)(b * 2048 + ic) * TSEG) + t) * PIX + q;
    float v0 = valid ? base[0] : 0.f;
    float v1 = valid ? base[(size_t)TSEG * PIX] : 0.f;
    __half2 hh;
    hh.x = __float2half_rn(v0);
    hh.y = __float2half_rn(v1);
    size_t o = (size_t)row * K18 + (size_t)kk * 2048 + ic;
    *(__half2*)(hi + o) = hh;
}

// ===================== ALL weight repacks in ONE launch =====================
__global__ void __launch_bounds__(128) repack_all_k(
    const float* s0, const float* s1, const float* s2, const float* s3,
    const float* s4, const float* s5, const float* s6, const float* s7,
    __half* d0, __half* d1, __half* d2, __half* d3,
    __half* d4, __half* d5, __half* d6, __half* d7)
{
    const int cum[9]    = {0, 8192, 10240, 26624, 30720, 38912, 47104, 49152, 51200};
    const int OCt[8]    = {1024, 512, 2048, 2048, 1024, 1024, 512, 512};
    const int stridet[8]= {2048, 1024, 2560, 2560, 2048, 2048, 1024, 1024};
    const int c0t[8]    = {0, 0, 0, 2048, 0, 0, 0, 0};
    const int ICt[8]    = {2048, 1024, 2048, 512, 2048, 2048, 1024, 1024};

    __shared__ float s[2304];
    int bid = blockIdx.x;
    int j = 0;
    while (bid >= cum[j + 1]) j++;
    int bi = bid - cum[j];
    const float* src = (j == 0) ? s0 : (j == 1) ? s1 : (j == 2) ? s2 : (j == 3) ? s3
                     : (j == 4) ? s4 : (j == 5) ? s5 : (j == 6) ? s6 : s7;
    __half* dst = (j == 0) ? d0 : (j == 1) ? d1 : (j == 2) ? d2 : (j == 3) ? d3
                : (j == 4) ? d4 : (j == 5) ? d5 : (j == 6) ? d6 : d7;
    int OC = OCt[j], IC = ICt[j], srcStride = stridet[j], c0 = c0t[j];

    int oc = bi % OC, ic0 = (bi / OC) * 256, tid = threadIdx.x;
    const float* base = src + ((size_t)oc * srcStride + c0 + ic0) * 9;
    for (int i = tid; i < 2304; i += 128) s[i] = base[i];
    __syncthreads();
    size_t dbase = (size_t)oc * ((size_t)IC * 9) + ic0 + 2 * tid;
#pragma unroll
    for (int kk = 0; kk < 9; kk++) {
        __half2 hh;
        hh.x = __float2half_rn(s[(2 * tid) * 9 + kk]);
        hh.y = __float2half_rn(s[(2 * tid + 1) * 9 + kk]);
        *(__half2*)(dst + dbase + (size_t)kk * IC) = hh;
    }
}

__global__ void bnconcat_k(const float* __restrict__ a, const float* __restrict__ b,
                           float* __restrict__ dst)
{
    int i = blockIdx.x * blockDim.x + threadIdx.x;
    if (i >= 4 * 2048) return;
    int pr = i / 2048, j = i - pr * 2048;
    dst[i] = (j < 1024) ? a[pr * 1024 + j] : b[pr * 1024 + (j - 1024)];
}

// ===================== small kernels =====================
__global__ void finish_k(const float* __restrict__ part, int nsplit, int chunk,
                         const float* __restrict__ bn, float* __restrict__ out,
                         int OC, int total, int postop)
{
    int i = blockIdx.x * blockDim.x + threadIdx.x;
    if (i >= total) return;
    float s = 0.f;
    for (int ks = 0; ks < nsplit; ks++) s += part[(size_t)ks * chunk + i];
    if (postop == 1) {
        int oc = (i / PIX) % OC;
        float g = bn[oc], b = bn[OC + oc], m = bn[2 * OC + oc], v = bn[3 * OC + oc];
        s = (s - m) * g * rsqrtf(v + 1e-5f) + b;
        s = fmaxf(s, 0.f);
    }
    out[i] = s;
}

__global__ void mask_final_k(const float* __restrict__ y2, const float* __restrict__ w3,
                             float* __restrict__ mask, float* __restrict__ outmask)
{
    int n = blockIdx.x;
    int p = threadIdx.x, g = threadIdx.y;
    int oh = p / 7, ow = p - oh * 7;
    float s = 0.f;
    for (int ic = g; ic < 512; ic += 8) {
        const float* row = y2 + ((size_t)n * 512 + ic) * PIX;
        const float* wr = w3 + ic * 9;
#pragma unroll
        for (int kh = 0; kh < 3; kh++)
#pragma unroll
            for (int kw = 0; kw < 3; kw++) {
                int ih = oh + kh - 1, iw = ow + kw - 1;
                if (ih >= 0 && ih < 7 && iw >= 0 && iw < 7)
                    s += row[ih * 7 + iw] * wr[kh * 3 + kw];
            }
    }
    __shared__ float red[8][49];
    red[g][p] = s;
    __syncthreads();
    if (g == 0) {
        float tot = 0.f;
#pragma unroll
        for (int q = 0; q < 8; q++) tot += red[q][p];
        float m = 1.f / (1.f + expf(-tot));
        mask[n * PIX + p] = m;
        outmask[n * PIX + p] = m;
    }
}

__global__ void mxmxc_k(const float* __restrict__ x, const float* __restrict__ mask,
                        float* __restrict__ mx, float* __restrict__ mxc)
{
    int bt = blockIdx.x;
    int c = blockIdx.y * 8 + threadIdx.y;
    int p = threadIdx.x;
    int b = bt / TSEG, t = bt - b * TSEG;
    float v = x[(((size_t)(b * 2048 + c)) * TSEG + t) * PIX + p] * mask[bt * PIX + p];
    mx[((size_t)bt * 2048 + c) * PIX + p] = v;
    __shared__ float red[8][49];
    red[threadIdx.y][p] = v;
    __syncthreads();
    if (p == 0) {
        float s = 0.f;
        for (int q = 0; q < 49; q++) s += red[threadIdx.y][q];
        mxc[bt * 2048 + c] = s * (1.f / (float)PIX);
    }
}

__global__ void meanxin_k(const float* __restrict__ mx, const float* __restrict__ aw,
                          float* __restrict__ meanx, float* __restrict__ xin)
{
    int i = blockIdx.x * blockDim.x + threadIdx.x;
    const int inner = 2048 * PIX;
    if (i >= 2 * inner) return;
    int b = i / inner, r = i - b * inner;
    float sm = 0.f, sx = 0.f;
    for (int t = 0; t < TSEG; t++) {
        float v = mx[((size_t)(b * TSEG + t)) * inner + r];
        sm += v;
        sx += aw[b * TSEG + t] * v;
    }
    meanx[i] = sm * (1.f / (float)TSEG);
    xin[i] = sx;
}

__global__ void attfea_k(const float* __restrict__ mxc, const float* __restrict__ wf,
                         float* __restrict__ attfea)
{
    int bt = blockIdx.x;
    int tid = threadIdx.x;
    __shared__ float sr[256];
    float s = 0.f;
    for (int c = tid; c < 2048; c += 256) s += mxc[bt * 2048 + c] * wf[c];
    sr[tid] = s;
    __syncthreads();
    for (int st = 128; st > 0; st >>= 1) {
        if (tid < st) sr[tid] += sr[tid + st];
        __syncthreads();
    }
    if (tid == 0) attfea[bt] = sr[0];
}

__global__ void aw_k(const float* __restrict__ attfea, float* __restrict__ aw,
                     float* __restrict__ out_aws)
{
    int b = threadIdx.x;
    if (b >= 2) return;
    float m = -1e30f;
    for (int t = 0; t < TSEG; t++) m = fmaxf(m, attfea[b * TSEG + t]);
    float sum = 0.f;
    for (int t = 0; t < TSEG; t++) sum += expf(attfea[b * TSEG + t] - m);
    for (int t = 0; t < TSEG; t++) {
        float a = expf(attfea[b * TSEG + t] - m) / sum;
        aw[b * TSEG + t] = a;
        out_aws[b * TSEG + t] = a;
    }
}

__global__ void ginit8_k(const float* __restrict__ part, const float* __restrict__ lstm_b,
                         float* __restrict__ gates0)
{
    int i = blockIdx.x * blockDim.x + threadIdx.x;
    const int total = 2 * 2048 * PIX;
    if (i >= total) return;
    int oc = (i / PIX) % 2048;
    float s = lstm_b[oc];
#pragma unroll
    for (int ks = 0; ks < 8; ks++) s += part[(size_t)ks * total + i];
    gates0[i] = s;
}

__global__ void final_k(const float* __restrict__ houts, const float* __restrict__ fc_w,
                        const float* __restrict__ fc_b, float* __restrict__ out)
{
    __shared__ float om[1024];
    int tid = threadIdx.x;
    for (int i = tid; i < 1024; i += 512) {
        int b = i / 512, c = i - b * 512;
        float s = 0.f;
        for (int t = 0; t < TSEG; t++) s += houts[((size_t)t * 2 + b) * 512 + c];
        om[i] = s * (1.f / (float)TSEG);
    }
    __syncthreads();
    for (int i = tid; i < 202; i += 512) {
        int b = i / 101, k = i - b * 101;
        float s = fc_b[k];
        for (int c = 0; c < 512; c++) s += om[b * 512 + c] * fc_w[k * 512 + c];
        out[i] = s;
    }
    if (tid == 0) { out[2402] = 0.f; out[2403] = 0.f; }
}

// ===================== host =====================
static float* symaddr(const void* sym) { void* p = nullptr; cudaGetSymbolAddress(&p, sym); return (float*)p; }
static __half* symaddrh(const void* sym) { void* p = nullptr; cudaGetSymbolAddress(&p, sym); return (__half*)p; }

#define GEMM_SMEM2 (3 * 32768)
#define GEMM_SMEM3 (3 * 49152)

extern "C" void kernel_launch(void* const* d_in, const int* in_sizes, int n_in,
                              void* d_out, int out_size)
{
    const float* x      = (const float*)d_in[0];
    const float* wf     = (const float*)d_in[1];
    const float* fc_w   = (const float*)d_in[3];
    const float* fc_b   = (const float*)d_in[4];
    const float* h0_w1  = (const float*)d_in[5];
    const float* h0_bn1 = (const float*)d_in[6];
    const float* h0_w2  = (const float*)d_in[7];
    const float* h0_bn2 = (const float*)d_in[8];
    const float* c0_w1  = (const float*)d_in[9];
    const float* c0_bn1 = (const float*)d_in[10];
    const float* c0_w2  = (const float*)d_in[11];
    const float* c0_bn2 = (const float*)d_in[12];
    const float* mk_w1  = (const float*)d_in[13];
    const float* mk_bn1 = (const float*)d_in[14];
    const float* mk_w2  = (const float*)d_in[15];
    const float* mk_bn2 = (const float*)d_in[16];
    const float* mk_w3  = (const float*)d_in[17];
    const float* lstm_w = (const float*)d_in[18];
    const float* lstm_b = (const float*)d_in[19];
    float* out = (float*)d_out;

    cudaFuncSetAttribute(gemm_mma_k<2>, cudaFuncAttributeMaxDynamicSharedMemorySize, GEMM_SMEM2);
    cudaFuncSetAttribute(gemm_mma_k<3>, cudaFuncAttributeMaxDynamicSharedMemorySize, GEMM_SMEM3);
    cudaFuncSetAttribute(lstm_loop_k, cudaFuncAttributeMaxDynamicSharedMemorySize, GEMM_SMEM3);

    float *mx = symaddr(g_mx), *xin = symaddr(g_xin);
    float *y2 = symaddr(g_y2), *mask = symaddr(g_mask);
    float *meanx = symaddr(g_meanx), *mxc = symaddr(g_mxc), *attfea = symaddr(g_attfea);
    float *aw = symaddr(g_aw), *h = symaddr(g_h), *cst = symaddr(g_cst);
    float *gates0 = symaddr(g_gates0), *part = symaddr(g_part), *houts = symaddr(g_houts);
    float *tmphc = symaddr(g_tmphc), *bnc1 = symaddr(g_bnc1);

    __half *axt_h = symaddrh(g_axt_h);
    __half *ay1_h = symaddrh(g_ay1_h);
    __half *sa_h = symaddrh(g_sa_h),   *sa_l = symaddrh(g_sa_l);
    __half *sb_h = symaddrh(g_sb_h),   *sb_l = symaddrh(g_sb_l);
    __half *slh_h = symaddrh(g_slh_h), *slh_l = symaddrh(g_slh_l);
    __half *wmk1_h = symaddrh(g_wmk1_h);
    __half *wmk2_h = symaddrh(g_wmk2_h);
    __half *wgx_h = symaddrh(g_wgx_h);
    __half *whc1_h = symaddrh(g_whc1_h);
    __half *w2h_h = symaddrh(g_w2h_h);
    __half *w2c_h = symaddrh(g_w2c_h);
    __half *wlh_h = symaddrh(g_wlh_h);

    auto blk = [](long long n) { return (unsigned)((n + 255) / 256); };
    dim3 cb(49, 8);
    const long long GCH = 2 * 2048 * PIX;
    const long long HCH = 2 * 512 * PIX;

    // ---- ALL weight repacks in one launch (hi only) ----
    repack_all_k<<<51200, 128>>>(mk_w1, mk_w2, lstm_w, lstm_w, h0_w1, c0_w1, h0_w2, c0_w2,
                                 wmk1_h, wmk2_h, wgx_h, wlh_h,
                                 whc1_h, whc1_h + (size_t)1024 * K18, w2h_h, w2c_h);
    bnconcat_k<<<32, 256>>>(h0_bn1, c0_bn1, bnc1);

    // ---- mask path ----
    im2colx_k<<<blk((long long)2156 * 9 * 1024), 256>>>(x, axt_h);
    {
        dim3 grid(8, 17, 1);
        gemm_mma_k<2><<<grid, 256, GEMM_SMEM2>>>(axt_h, nullptr, wmk1_h, part, K18, K18, 2156, 1024,
                                                 mk_bn1, 2, 0, ay1_h,
                                                 nullptr, nullptr, nullptr, nullptr, 0);
    }
    {
        dim3 grid(4, 17, 2);
        gemm_mma_k<2><<<grid, 256, GEMM_SMEM2>>>(ay1_h, nullptr, wmk2_h, part, K9, K9 / 2, 2156, 512,
                                                 nullptr, 0, (long long)44 * 512 * PIX, nullptr,
                                                 nullptr, nullptr, nullptr, nullptr, 0);
    }
    finish_k<<<blk((long long)44 * 512 * PIX), 256>>>(part, 2, 44 * 512 * PIX, mk_bn2, y2,
                                                      512, 44 * 512 * PIX, 1);
    mask_final_k<<<NBT, cb>>>(y2, mk_w3, mask, out + 246);

    // ---- masked features + attention ----
    mxmxc_k<<<dim3(NBT, 256), cb>>>(x, mask, mx, mxc);
    attfea_k<<<NBT, 256>>>(mxc, wf, attfea);
    aw_k<<<1, 32>>>(attfea, aw, out + 202);
    meanxin_k<<<blk(2 * 2048 * PIX), 256>>>(mx, aw, meanx, xin);

    // ---- xin GEMM + hc1 GEMM merged (z-multiplex) ----
    im2col_k<<<blk((long long)98 * 9 * 1024), 256>>>(xin, 2048, 0, 2048, 98, sa_h, sa_l);
    im2col_k<<<blk((long long)98 * 9 * 1024), 256>>>(meanx, 2048, 0, 2048, 98, sb_h, sb_l);
    {
        dim3 grid(16, 1, 16);
        gemm_mma_k<3><<<grid, 256, GEMM_SMEM3>>>(sa_h, sa_l, wgx_h, part, K18, K18 / 8, 98, 2048,
                                                 nullptr, 0, GCH, nullptr,
                                                 sb_h, sb_l, whc1_h, part + 8 * GCH, 8);
    }
    ginit8_k<<<blk(GCH), 256>>>(part, lstm_b, gates0);
    finish_k<<<blk(GCH), 256>>>(part + 8 * GCH, 8, (int)GCH, bnc1, tmphc, 2048, (int)GCH, 1);

    // ---- hc2: both branches in ONE launch ----
    im2col_k<<<blk((long long)98 * 9 * 512), 256>>>(tmphc, 2048, 0, 1024, 98, sa_h, sa_l);
    im2col_k<<<blk((long long)98 * 9 * 512), 256>>>(tmphc, 2048, 1024, 1024, 98, sb_h, sb_l);
    {
        dim3 grid(4, 1, 8);
        gemm_mma_k<3><<<grid, 256, GEMM_SMEM3>>>(sa_h, sa_l, w2h_h, part, K9, K9 / 4, 98, 512,
                                                 nullptr, 0, HCH, nullptr,
                                                 sb_h, sb_l, w2c_h, part + 4 * HCH, 4);
    }
    finish_k<<<blk(HCH), 256>>>(part, 4, (int)HCH, h0_bn2, h, 512, (int)HCH, 1);
    finish_k<<<blk(HCH), 256>>>(part + 4 * HCH, 4, (int)HCH, c0_bn2, cst, 512, (int)HCH, 1);

    // ---- seed im2col for h0, then the WHOLE recurrence in ONE persistent kernel ----
    im2col_k<<<blk((long long)98 * 9 * 256), 256>>>(h, 512, 0, 512, 98, slh_h, slh_l);
    zerobar_k<<<1, 1>>>();
    lstm_loop_k<<<128, 256, GEMM_SMEM3>>>(slh_h, slh_l, wlh_h, part, gates0, cst, houts);

    final_k<<<1, 512>>>(houts, fc_w, fc_b, out);
}

// round 17
// speedup vs baseline: 1.1378x; 1.1193x over previous
#include <cuda_runtime.h>
#include <cuda_fp16.h>
#include <cstdint>

// ===================== problem constants =====================
#define TSEG 22
#define NBT  44
#define PIX  49
#define K18  18432     // 9*2048
#define K9   9216      // 9*1024
#define K45  4608      // 9*512
#define AM   2176      // 17*128 pad of 2156

// ===================== fp32 scratch =====================
__device__ float g_mx[(size_t)NBT * 2048 * PIX];
__device__ float g_xin[2 * 2048 * PIX];
__device__ float g_y2[(size_t)NBT * 512 * PIX];
__device__ float g_mask[NBT * PIX];
__device__ float g_meanx[2 * 2048 * PIX];
__device__ float g_mxc[NBT * 2048];
__device__ float g_attfea[NBT];
__device__ float g_aw[NBT];
__device__ float g_h[2 * 512 * PIX];
__device__ float g_cst[2 * 512 * PIX];
__device__ float g_gates0[2 * 2048 * PIX];
__device__ float g_part[3300000];
__device__ float g_houts[TSEG * 2 * 512];
__device__ float g_tmphc[2 * 2048 * PIX];
__device__ float g_bnc1[4 * 2048];
__device__ unsigned g_gbar;

// ===================== split-fp16 buffers (zero-init at module load) ==========
__device__ __half g_axt_h[(size_t)AM * K18];
__device__ __half g_ay1_h[(size_t)AM * K9];
__device__ __half g_sa_h[(size_t)128 * K18],  g_sa_l[(size_t)128 * K18];
__device__ __half g_sb_h[(size_t)128 * K18],  g_sb_l[(size_t)128 * K18];
__device__ __half g_slh_h[(size_t)128 * K45], g_slh_l[(size_t)128 * K45];
__device__ __half g_wmk1_h[(size_t)1024 * K18];
__device__ __half g_wmk2_h[(size_t)512 * K9];
__device__ __half g_wgx_h[(size_t)2048 * K18];
__device__ __half g_whc1_h[(size_t)2048 * K18];
__device__ __half g_w2h_h[(size_t)512 * K9];
__device__ __half g_w2c_h[(size_t)512 * K9];
__device__ __half g_wlh_h[(size_t)2048 * K45];

// ===================== base-ISA tensor helpers (sm_80+) =====================
__device__ __forceinline__ uint32_t smem_u32(const void* p) {
    uint32_t a;
    asm("{ .reg .u64 t; cvta.to.shared.u64 t, %1; cvt.u32.u64 %0, t; }" : "=r"(a) : "l"(p));
    return a;
}
__device__ __forceinline__ void ldsm4(uint32_t* r, uint32_t addr) {
    asm volatile("ldmatrix.sync.aligned.m8n8.x4.shared.b16 {%0,%1,%2,%3}, [%4];"
        : "=r"(r[0]), "=r"(r[1]), "=r"(r[2]), "=r"(r[3]) : "r"(addr));
}
__device__ __forceinline__ void mma16816(float* d, const uint32_t* a, const uint32_t* b) {
    asm volatile(
        "mma.sync.aligned.m16n8k16.row.col.f32.f16.f16.f32 "
        "{%0,%1,%2,%3}, {%4,%5,%6,%7}, {%8,%9}, {%0,%1,%2,%3};"
        : "+f"(d[0]), "+f"(d[1]), "+f"(d[2]), "+f"(d[3])
        : "r"(a[0]), "r"(a[1]), "r"(a[2]), "r"(a[3]), "r"(b[0]), "r"(b[1]));
}
#define CP_COMMIT() asm volatile("cp.async.commit_group;" ::: "memory")

__device__ __forceinline__ void split_h(float v, __half& h, __half& l) {
    h = __float2half_rn(v);
    l = __float2half_rn(v - __half2float(h));
}

// ===================== split-fp16 mma.sync GEMM (round-13 config) =====================
// NT=2: D = Ahi @ Bhi^T (1 term).  NT=3: D = (Ahi+Alo) @ Bhi^T (2 terms).
// grid (N/128, ceil(M/128), z), block 256 (8 warps, 2x4 -> 64x32/warp), 3-stage ring.
// postop: 0 raw fp32, 1 BN+ReLU fp32, 2 BN+ReLU scattered fp16-hi im2col.
template<int NT>
__global__ void __launch_bounds__(256, 1) gemm_mma_k(
    const __half* Ahi, const __half* Alo, const __half* Bhi,
    float* outp, int K, int Ktile, int Mreal, int OCtot,
    const float* __restrict__ bn, int postop, long long partChunk,
    __half* __restrict__ ic_h,
    const __half* A2hi, const __half* A2lo, const __half* B2hi,
    float* out2, int zhalf)
{
    extern __shared__ char dsm[];
    __shared__ float s_sc[128], s_sh[128];
    const uint32_t STG = (uint32_t)NT * 16384u;
    const uint32_t OFF_BH = (NT == 2) ? 16384u : 32768u;

    int tid = threadIdx.x, lane = tid & 31, wid = tid >> 5;
    int wm = wid & 1, wn = wid >> 1;
    uint32_t sbase = smem_u32(dsm);

    int zz = blockIdx.z;
    if (zhalf > 0 && zz >= zhalf) {
        Ahi = A2hi; Alo = A2lo; Bhi = B2hi; outp = out2; zz -= zhalf;
    }

    int n0 = blockIdx.x * 128;
    int m0 = blockIdx.y * 128;
    long long kc0 = (long long)zz * Ktile;
    int nChunks = Ktile / 64;

    const __half* tbase[NT == 2 ? 2 : 3];
    tbase[0] = Ahi + (size_t)m0 * K + kc0;
    if (NT == 2) {
        tbase[1] = Bhi + (size_t)n0 * K + kc0;
    } else {
        tbase[1] = Alo + (size_t)m0 * K + kc0;
        tbase[2] = Bhi + (size_t)n0 * K + kc0;
    }

    auto load_chunk = [&](int c, int stg) {
        uint32_t dbase = sbase + (uint32_t)stg * STG;
#pragma unroll
        for (int j = 0; j < NT * 4; j++) {
            int tile = j >> 2;
            int within = ((j & 3) << 8) + tid;
            int r = within >> 3, cs = within & 7;
            const void* g = tbase[tile] + (size_t)c * 64 + (size_t)r * K + cs * 8;
            uint32_t so = dbase + (uint32_t)tile * 16384u
                        + (uint32_t)(r * 128 + ((cs * 16) ^ ((r & 7) * 16)));
            asm volatile("cp.async.cg.shared.global [%0], [%1], 16;" :: "r"(so), "l"(g));
        }
    };

    float d[4][4][4];
#pragma unroll
    for (int a = 0; a < 4; a++)
#pragma unroll
        for (int b = 0; b < 4; b++)
#pragma unroll
            for (int c = 0; c < 4; c++) d[a][b][c] = 0.f;

    if (nChunks > 0) { load_chunk(0, 0); CP_COMMIT(); }
    if (nChunks > 1) { load_chunk(1, 1); CP_COMMIT(); }

    for (int c = 0; c < nChunks; c++) {
        if (c + 1 < nChunks) asm volatile("cp.async.wait_group 1;" ::: "memory");
        else                 asm volatile("cp.async.wait_group 0;" ::: "memory");
        __syncthreads();
        if (c + 2 < nChunks) { load_chunk(c + 2, (c + 2) % 3); CP_COMMIT(); }

        int stg = c % 3;
        uint32_t sAh = sbase + (uint32_t)stg * STG;
        uint32_t sAl = sAh + 16384u;
        uint32_t sBh = sAh + OFF_BH;

#pragma unroll
        for (int k16 = 0; k16 < 4; k16++) {
            uint32_t ah[4][4], al[4][4], bh[4][2];
#pragma unroll
            for (int mt = 0; mt < 4; mt++) {
                uint32_t r = (uint32_t)(wm * 64 + mt * 16 + (lane & 15));
                uint32_t cby = (uint32_t)(k16 * 32 + ((lane >> 4) << 4));
                uint32_t off = r * 128 + (cby ^ ((r & 7) << 4));
                ldsm4(ah[mt], sAh + off);
                if (NT >= 3) ldsm4(al[mt], sAl + off);
            }
#pragma unroll
            for (int p = 0; p < 2; p++) {
                uint32_t r = (uint32_t)(wn * 32 + p * 16 + (((lane >> 4) & 1) << 3) + (lane & 7));
                uint32_t cby = (uint32_t)(k16 * 32 + (((lane >> 3) & 1) << 4));
                uint32_t off = r * 128 + (cby ^ ((r & 7) << 4));
                uint32_t t4[4];
                ldsm4(t4, sBh + off);
                bh[2 * p][0] = t4[0]; bh[2 * p][1] = t4[1];
                bh[2 * p + 1][0] = t4[2]; bh[2 * p + 1][1] = t4[3];
            }
#pragma unroll
            for (int mt = 0; mt < 4; mt++)
#pragma unroll
                for (int nt = 0; nt < 4; nt++) {
                    mma16816(d[mt][nt], ah[mt], bh[nt]);
                    if (NT >= 3) mma16816(d[mt][nt], al[mt], bh[nt]);
                }
        }
        __syncthreads();
    }

    if (postop >= 1 && tid < 128) {
        int oc = n0 + tid;
        float g = bn[oc], b = bn[OCtot + oc], m = bn[2 * OCtot + oc], v = bn[3 * OCtot + oc];
        float sc = g * rsqrtf(v + 1e-5f);
        s_sc[tid] = sc;
        s_sh[tid] = b - m * sc;
    }
    __syncthreads();

    if (postop == 2) {
        int Kdst = OCtot * 9;
#pragma unroll
        for (int mt = 0; mt < 4; mt++) {
#pragma unroll
            for (int nt = 0; nt < 4; nt++) {
                int ln = wn * 32 + nt * 8 + 2 * (lane & 3);
                int r0 = m0 + wm * 64 + mt * 16 + (lane >> 2);
#pragma unroll
                for (int half = 0; half < 2; half++) {
                    int mrow = r0 + half * 8;
                    if (mrow < Mreal) {
                        int img = mrow / 49, p = mrow - img * 49;
                        float v0 = fmaxf(d[mt][nt][half * 2 + 0] * s_sc[ln] + s_sh[ln], 0.f);
                        float v1 = fmaxf(d[mt][nt][half * 2 + 1] * s_sc[ln + 1] + s_sh[ln + 1], 0.f);
                        __half2 hh;
                        hh.x = __float2half_rn(v0);
                        hh.y = __float2half_rn(v1);
                        int qh = p / 7, qw = p - qh * 7;
                        int oc = n0 + ln;
#pragma unroll
                        for (int kk = 0; kk < 9; kk++) {
                            int oh = qh - (kk / 3 - 1), ow = qw - (kk % 3 - 1);
                            if (oh >= 0 && oh < 7 && ow >= 0 && ow < 7) {
                                size_t o = (size_t)(img * 49 + oh * 7 + ow) * Kdst + kk * OCtot + oc;
                                *(__half2*)(ic_h + o) = hh;
                            }
                        }
                    }
                }
            }
        }
        return;
    }

    float* obase0 = outp + (size_t)zz * partChunk;
#pragma unroll
    for (int mt = 0; mt < 4; mt++) {
#pragma unroll
        for (int nt = 0; nt < 4; nt++) {
            int ln = wn * 32 + nt * 8 + 2 * (lane & 3);
            int r0 = m0 + wm * 64 + mt * 16 + (lane >> 2);
#pragma unroll
            for (int half = 0; half < 2; half++) {
                int mrow = r0 + half * 8;
                if (mrow < Mreal) {
                    int img = mrow / 49, p = mrow - img * 49;
                    float* ob = obase0 + ((size_t)img * OCtot + n0) * 49 + p;
                    float v0 = d[mt][nt][half * 2 + 0];
                    float v1 = d[mt][nt][half * 2 + 1];
                    if (postop) {
                        v0 = fmaxf(v0 * s_sc[ln] + s_sh[ln], 0.f);
                        v1 = fmaxf(v1 * s_sc[ln + 1] + s_sh[ln + 1], 0.f);
                    }
                    ob[(size_t)ln * 49] = v0;
                    ob[(size_t)(ln + 1) * 49] = v1;
                }
            }
        }
    }
}

// ===================== PERSISTENT fused recurrence =====================
// grid 128 (16 n-tiles x 8 k-splits), block 256, 96KB smem -> all co-resident.
// Loop GEMM is 1-term (A = h in fp16-hi only; weight hi only) — measured-error
// budget from rounds 11-13 supports this. Barrier: atomic arrive + volatile-load
// poll (no atomic spin), threadfence-acquire on exit.
__global__ void zerobar_k() { g_gbar = 0u; }

__device__ __forceinline__ void global_bar(unsigned target) {
    __syncthreads();
    if (threadIdx.x == 0) {
        __threadfence();
        atomicAdd(&g_gbar, 1u);
        volatile unsigned* p = &g_gbar;
        while (*p < target) { }
        __threadfence();
    }
    __syncthreads();
}

__global__ void __launch_bounds__(256, 1) lstm_loop_k(
    __half* __restrict__ slh_h,
    const __half* __restrict__ wlh,
    float* __restrict__ part, const float* __restrict__ gates0,
    const float* __restrict__ cst0, float* __restrict__ houts)
{
    extern __shared__ char dsm[];            // 3 stages x 2 tiles x 16KB = 96KB
    int tid = threadIdx.x, lane = tid & 31, wid = tid >> 5;
    int wm = wid & 1, wn = wid >> 1;
    uint32_t sbase = smem_u32(dsm);

    int ntile = blockIdx.x & 15, ks = blockIdx.x >> 4;
    int n0 = ntile * 128;
    long long kc0 = (long long)ks * 576;     // Ktile = 4608/8
    const long long GCH = 2LL * 2048 * PIX;

    // phase-B persistent state: warp owns (b,c) pair; cell state in registers
    int pairi = blockIdx.x * 8 + wid;        // 0..1023
    int pb = pairi >> 9, pc = pairi & 511;
    float cstate[2];
    {
        size_t hb = ((size_t)pb * 512 + pc) * PIX;
        cstate[0] = (lane < 49) ? cst0[hb + lane] : 0.f;
        cstate[1] = (lane + 32 < 49) ? cst0[hb + lane + 32] : 0.f;
    }

    unsigned barcnt = 0;

    for (int t = 0; t < TSEG; t++) {
        // ================= phase A: 1-term GEMM partial =================
        const __half* tb0 = slh_h + kc0;                      // m0 = 0
        const __half* tb1 = wlh + (size_t)n0 * K45 + kc0;

        auto load_chunk = [&](int c, int stg) {
            uint32_t dbase = sbase + (uint32_t)stg * 32768u;
#pragma unroll
            for (int j = 0; j < 8; j++) {
                int tile = j >> 2;
                int within = ((j & 3) << 8) + tid;
                int r = within >> 3, cs = within & 7;
                const __half* tb = (tile == 0) ? tb0 : tb1;
                const void* g = tb + (size_t)c * 64 + (size_t)r * K45 + cs * 8;
                uint32_t so = dbase + (uint32_t)tile * 16384u
                            + (uint32_t)(r * 128 + ((cs * 16) ^ ((r & 7) * 16)));
                asm volatile("cp.async.cg.shared.global [%0], [%1], 16;" :: "r"(so), "l"(g));
            }
        };

        float d[4][4][4];
#pragma unroll
        for (int a = 0; a < 4; a++)
#pragma unroll
            for (int b = 0; b < 4; b++)
#pragma unroll
                for (int c = 0; c < 4; c++) d[a][b][c] = 0.f;

        load_chunk(0, 0); CP_COMMIT();
        load_chunk(1, 1); CP_COMMIT();

        for (int c = 0; c < 9; c++) {
            if (c + 1 < 9) asm volatile("cp.async.wait_group 1;" ::: "memory");
            else           asm volatile("cp.async.wait_group 0;" ::: "memory");
            __syncthreads();
            if (c + 2 < 9) { load_chunk(c + 2, (c + 2) % 3); CP_COMMIT(); }

            int stg = c % 3;
            uint32_t sAh = sbase + (uint32_t)stg * 32768u;
            uint32_t sBh = sAh + 16384u;

#pragma unroll
            for (int k16 = 0; k16 < 4; k16++) {
                uint32_t ah[4][4], bh[4][2];
#pragma unroll
                for (int mt = 0; mt < 4; mt++) {
                    uint32_t r = (uint32_t)(wm * 64 + mt * 16 + (lane & 15));
                    uint32_t cby = (uint32_t)(k16 * 32 + ((lane >> 4) << 4));
                    uint32_t off = r * 128 + (cby ^ ((r & 7) << 4));
                    ldsm4(ah[mt], sAh + off);
                }
#pragma unroll
                for (int p = 0; p < 2; p++) {
                    uint32_t r = (uint32_t)(wn * 32 + p * 16 + (((lane >> 4) & 1) << 3) + (lane & 7));
                    uint32_t cby = (uint32_t)(k16 * 32 + (((lane >> 3) & 1) << 4));
                    uint32_t off = r * 128 + (cby ^ ((r & 7) << 4));
                    uint32_t t4[4];
                    ldsm4(t4, sBh + off);
                    bh[2 * p][0] = t4[0]; bh[2 * p][1] = t4[1];
                    bh[2 * p + 1][0] = t4[2]; bh[2 * p + 1][1] = t4[3];
                }
#pragma unroll
                for (int mt = 0; mt < 4; mt++)
#pragma unroll
                    for (int nt = 0; nt < 4; nt++)
                        mma16816(d[mt][nt], ah[mt], bh[nt]);
            }
            __syncthreads();
        }

        // write raw fp32 partial
        float* obase0 = part + (size_t)ks * GCH;
#pragma unroll
        for (int mt = 0; mt < 4; mt++) {
#pragma unroll
            for (int nt = 0; nt < 4; nt++) {
                int ln = wn * 32 + nt * 8 + 2 * (lane & 3);
                int r0 = wm * 64 + mt * 16 + (lane >> 2);
#pragma unroll
                for (int half = 0; half < 2; half++) {
                    int mrow = r0 + half * 8;
                    if (mrow < 98) {
                        int img = mrow / 49, p = mrow - img * 49;
                        float* ob = obase0 + ((size_t)img * 2048 + n0) * 49 + p;
                        ob[(size_t)ln * 49] = d[mt][nt][half * 2 + 0];
                        ob[(size_t)(ln + 1) * 49] = d[mt][nt][half * 2 + 1];
                    }
                }
            }
        }

        barcnt++; global_bar(barcnt * 128u);

        // ================= phase B: LSTM pointwise =================
        float hs[2];
#pragma unroll
        for (int s = 0; s < 2; s++) {
            int p = lane + 32 * s;
            float h2v = 0.f;
            if (p < 49) {
                size_t base = ((size_t)pb * 2048) * PIX + p;
                float gi = gates0[base + (size_t)pc * PIX];
                float gf = gates0[base + (size_t)(512 + pc) * PIX];
                float go = gates0[base + (size_t)(1024 + pc) * PIX];
                float gg = gates0[base + (size_t)(1536 + pc) * PIX];
#pragma unroll
                for (int k2 = 0; k2 < 8; k2++) {
                    size_t pbs = ((size_t)(k2 * 2 + pb) * 2048) * PIX + p;
                    gi += __ldcg(part + pbs + (size_t)pc * PIX);
                    gf += __ldcg(part + pbs + (size_t)(512 + pc) * PIX);
                    go += __ldcg(part + pbs + (size_t)(1024 + pc) * PIX);
                    gg += __ldcg(part + pbs + (size_t)(1536 + pc) * PIX);
                }
                float si = 1.f / (1.f + expf(-gi));
                float sf = 1.f / (1.f + expf(-gf));
                float so = 1.f / (1.f + expf(-go));
                float c2 = sf * cstate[s] + si * tanhf(gg);
                h2v = so * tanhf(c2);
                cstate[s] = c2;
                __half hh = __float2half_rn(h2v);
                int qh = p / 7, qw = p - qh * 7;
#pragma unroll
                for (int kk = 0; kk < 9; kk++) {
                    int oh = qh - (kk / 3 - 1), ow = qw - (kk % 3 - 1);
                    if (oh >= 0 && oh < 7 && ow >= 0 && ow < 7) {
                        size_t o = (size_t)(pb * 49 + oh * 7 + ow) * K45 + kk * 512 + pc;
                        slh_h[o] = hh;
                    }
                }
            }
            float r = h2v;
#pragma unroll
            for (int off = 16; off > 0; off >>= 1)
                r += __shfl_down_sync(0xffffffffu, r, off);
            hs[s] = r;
        }
        if (lane == 0)
            houts[((size_t)t * 2 + pb) * 512 + pc] = (hs[0] + hs[1]) * (1.f / (float)PIX);

        barcnt++; global_bar(barcnt * 128u);
    }
}

// ===================== im2col (fp32 (img,CHtot,49) -> split fp16) =====================
__global__ void im2col_k(const float* __restrict__ in, int CHtot, int c0, int IC, int nRows,
                         __half* __restrict__ hi, __half* __restrict__ lo)
{
    int ICp = IC >> 1;
    long long idx = (long long)blockIdx.x * blockDim.x + threadIdx.x;
    long long tot = (long long)nRows * 9 * ICp;
    if (idx >= tot) return;
    int icp = (int)(idx % ICp);
    long long r2 = idx / ICp;
    int kk = (int)(r2 % 9);
    int row = (int)(r2 / 9);
    int img = row / 49, p = row - img * 49;
    int oh = p / 7, ow = p - oh * 7;
    int ih = oh + kk / 3 - 1, iw = ow + kk % 3 - 1;
    bool valid = (ih >= 0) && (ih < 7) && (iw >= 0) && (iw < 7);
    int q = valid ? (ih * 7 + iw) : 0;
    int ic = icp * 2;
    const float* base = in + ((size_t)img * CHtot + c0 + ic) * PIX + q;
    float v0 = valid ? base[0] : 0.f;
    float v1 = valid ? base[PIX] : 0.f;
    __half2 hh, ll;
    split_h(v0, hh.x, ll.x);
    split_h(v1, hh.y, ll.y);
    size_t o = (size_t)row * (IC * 9) + (size_t)kk * IC + ic;
    *(__half2*)(hi + o) = hh;
    if (lo) *(__half2*)(lo + o) = ll;
}

// im2col reading x (B, 2048, T, 7, 7) directly (fused transpose); hi only
__global__ void im2colx_k(const float* __restrict__ x, __half* __restrict__ hi)
{
    const int ICp = 1024;
    long long idx = (long long)blockIdx.x * blockDim.x + threadIdx.x;
    long long tot = (long long)2156 * 9 * ICp;
    if (idx >= tot) return;
    int icp = (int)(idx % ICp);
    long long r2 = idx / ICp;
    int kk = (int)(r2 % 9);
    int row = (int)(r2 / 9);
    int img = row / 49, p = row - img * 49;
    int b = img / TSEG, t = img - b * TSEG;
    int oh = p / 7, ow = p - oh * 7;
    int ih = oh + kk / 3 - 1, iw = ow + kk % 3 - 1;
    bool valid = (ih >= 0) && (ih < 7) && (iw >= 0) && (iw < 7);
    int q = valid ? (ih * 7 + iw) : 0;
    int ic = icp * 2;
    const float* base = x + (((size_t)(b * 2048 + ic) * TSEG) + t) * PIX + q;
    float v0 = valid ? base[0] : 0.f;
    float v1 = valid ? base[(size_t)TSEG * PIX] : 0.f;
    __half2 hh;
    hh.x = __float2half_rn(v0);
    hh.y = __float2half_rn(v1);
    size_t o = (size_t)row * K18 + (size_t)kk * 2048 + ic;
    *(__half2*)(hi + o) = hh;
}

// ===================== ALL weight repacks in ONE launch =====================
__global__ void __launch_bounds__(128) repack_all_k(
    const float* s0, const float* s1, const float* s2, const float* s3,
    const float* s4, const float* s5, const float* s6, const float* s7,
    __half* d0, __half* d1, __half* d2, __half* d3,
    __half* d4, __half* d5, __half* d6, __half* d7)
{
    const int cum[9]    = {0, 8192, 10240, 26624, 30720, 38912, 47104, 49152, 51200};
    const int OCt[8]    = {1024, 512, 2048, 2048, 1024, 1024, 512, 512};
    const int stridet[8]= {2048, 1024, 2560, 2560, 2048, 2048, 1024, 1024};
    const int c0t[8]    = {0, 0, 0, 2048, 0, 0, 0, 0};
    const int ICt[8]    = {2048, 1024, 2048, 512, 2048, 2048, 1024, 1024};

    __shared__ float s[2304];
    int bid = blockIdx.x;
    int j = 0;
    while (bid >= cum[j + 1]) j++;
    int bi = bid - cum[j];
    const float* src = (j == 0) ? s0 : (j == 1) ? s1 : (j == 2) ? s2 : (j == 3) ? s3
                     : (j == 4) ? s4 : (j == 5) ? s5 : (j == 6) ? s6 : s7;
    __half* dst = (j == 0) ? d0 : (j == 1) ? d1 : (j == 2) ? d2 : (j == 3) ? d3
                : (j == 4) ? d4 : (j == 5) ? d5 : (j == 6) ? d6 : d7;
    int OC = OCt[j], IC = ICt[j], srcStride = stridet[j], c0 = c0t[j];

    int oc = bi % OC, ic0 = (bi / OC) * 256, tid = threadIdx.x;
    const float* base = src + ((size_t)oc * srcStride + c0 + ic0) * 9;
    for (int i = tid; i < 2304; i += 128) s[i] = base[i];
    __syncthreads();
    size_t dbase = (size_t)oc * ((size_t)IC * 9) + ic0 + 2 * tid;
#pragma unroll
    for (int kk = 0; kk < 9; kk++) {
        __half2 hh;
        hh.x = __float2half_rn(s[(2 * tid) * 9 + kk]);
        hh.y = __float2half_rn(s[(2 * tid + 1) * 9 + kk]);
        *(__half2*)(dst + dbase + (size_t)kk * IC) = hh;
    }
}

__global__ void bnconcat_k(const float* __restrict__ a, const float* __restrict__ b,
                           float* __restrict__ dst)
{
    int i = blockIdx.x * blockDim.x + threadIdx.x;
    if (i >= 4 * 2048) return;
    int pr = i / 2048, j = i - pr * 2048;
    dst[i] = (j < 1024) ? a[pr * 1024 + j] : b[pr * 1024 + (j - 1024)];
}

// ===================== small kernels =====================
__global__ void finish_k(const float* __restrict__ part, int nsplit, int chunk,
                         const float* __restrict__ bn, float* __restrict__ out,
                         int OC, int total, int postop)
{
    int i = blockIdx.x * blockDim.x + threadIdx.x;
    if (i >= total) return;
    float s = 0.f;
    for (int ks = 0; ks < nsplit; ks++) s += part[(size_t)ks * chunk + i];
    if (postop == 1) {
        int oc = (i / PIX) % OC;
        float g = bn[oc], b = bn[OC + oc], m = bn[2 * OC + oc], v = bn[3 * OC + oc];
        s = (s - m) * g * rsqrtf(v + 1e-5f) + b;
        s = fmaxf(s, 0.f);
    }
    out[i] = s;
}

__global__ void mask_final_k(const float* __restrict__ y2, const float* __restrict__ w3,
                             float* __restrict__ mask, float* __restrict__ outmask)
{
    int n = blockIdx.x;
    int p = threadIdx.x, g = threadIdx.y;
    int oh = p / 7, ow = p - oh * 7;
    float s = 0.f;
    for (int ic = g; ic < 512; ic += 8) {
        const float* row = y2 + ((size_t)n * 512 + ic) * PIX;
        const float* wr = w3 + ic * 9;
#pragma unroll
        for (int kh = 0; kh < 3; kh++)
#pragma unroll
            for (int kw = 0; kw < 3; kw++) {
                int ih = oh + kh - 1, iw = ow + kw - 1;
                if (ih >= 0 && ih < 7 && iw >= 0 && iw < 7)
                    s += row[ih * 7 + iw] * wr[kh * 3 + kw];
            }
    }
    __shared__ float red[8][49];
    red[g][p] = s;
    __syncthreads();
    if (g == 0) {
        float tot = 0.f;
#pragma unroll
        for (int q = 0; q < 8; q++) tot += red[q][p];
        float m = 1.f / (1.f + expf(-tot));
        mask[n * PIX + p] = m;
        outmask[n * PIX + p] = m;
    }
}

__global__ void mxmxc_k(const float* __restrict__ x, const float* __restrict__ mask,
                        float* __restrict__ mx, float* __restrict__ mxc)
{
    int bt = blockIdx.x;
    int c = blockIdx.y * 8 + threadIdx.y;
    int p = threadIdx.x;
    int b = bt / TSEG, t = bt - b * TSEG;
    float v = x[(((size_t)(b * 2048 + c)) * TSEG + t) * PIX + p] * mask[bt * PIX + p];
    mx[((size_t)bt * 2048 + c) * PIX + p] = v;
    __shared__ float red[8][49];
    red[threadIdx.y][p] = v;
    __syncthreads();
    if (p == 0) {
        float s = 0.f;
        for (int q = 0; q < 49; q++) s += red[threadIdx.y][q];
        mxc[bt * 2048 + c] = s * (1.f / (float)PIX);
    }
}

__global__ void meanxin_k(const float* __restrict__ mx, const float* __restrict__ aw,
                          float* __restrict__ meanx, float* __restrict__ xin)
{
    int i = blockIdx.x * blockDim.x + threadIdx.x;
    const int inner = 2048 * PIX;
    if (i >= 2 * inner) return;
    int b = i / inner, r = i - b * inner;
    float sm = 0.f, sx = 0.f;
    for (int t = 0; t < TSEG; t++) {
        float v = mx[((size_t)(b * TSEG + t)) * inner + r];
        sm += v;
        sx += aw[b * TSEG + t] * v;
    }
    meanx[i] = sm * (1.f / (float)TSEG);
    xin[i] = sx;
}

__global__ void attfea_k(const float* __restrict__ mxc, const float* __restrict__ wf,
                         float* __restrict__ attfea)
{
    int bt = blockIdx.x;
    int tid = threadIdx.x;
    __shared__ float sr[256];
    float s = 0.f;
    for (int c = tid; c < 2048; c += 256) s += mxc[bt * 2048 + c] * wf[c];
    sr[tid] = s;
    __syncthreads();
    for (int st = 128; st > 0; st >>= 1) {
        if (tid < st) sr[tid] += sr[tid + st];
        __syncthreads();
    }
    if (tid == 0) attfea[bt] = sr[0];
}

__global__ void aw_k(const float* __restrict__ attfea, float* __restrict__ aw,
                     float* __restrict__ out_aws)
{
    int b = threadIdx.x;
    if (b >= 2) return;
    float m = -1e30f;
    for (int t = 0; t < TSEG; t++) m = fmaxf(m, attfea[b * TSEG + t]);
    float sum = 0.f;
    for (int t = 0; t < TSEG; t++) sum += expf(attfea[b * TSEG + t] - m);
    for (int t = 0; t < TSEG; t++) {
        float a = expf(attfea[b * TSEG + t] - m) / sum;
        aw[b * TSEG + t] = a;
        out_aws[b * TSEG + t] = a;
    }
}

__global__ void ginit8_k(const float* __restrict__ part, const float* __restrict__ lstm_b,
                         float* __restrict__ gates0)
{
    int i = blockIdx.x * blockDim.x + threadIdx.x;
    const int total = 2 * 2048 * PIX;
    if (i >= total) return;
    int oc = (i / PIX) % 2048;
    float s = lstm_b[oc];
#pragma unroll
    for (int ks = 0; ks < 8; ks++) s += part[(size_t)ks * total + i];
    gates0[i] = s;
}

__global__ void final_k(const float* __restrict__ houts, const float* __restrict__ fc_w,
                        const float* __restrict__ fc_b, float* __restrict__ out)
{
    __shared__ float om[1024];
    int tid = threadIdx.x;
    for (int i = tid; i < 1024; i += 512) {
        int b = i / 512, c = i - b * 512;
        float s = 0.f;
        for (int t = 0; t < TSEG; t++) s += houts[((size_t)t * 2 + b) * 512 + c];
        om[i] = s * (1.f / (float)TSEG);
    }
    __syncthreads();
    for (int i = tid; i < 202; i += 512) {
        int b = i / 101, k = i - b * 101;
        float s = fc_b[k];
        for (int c = 0; c < 512; c++) s += om[b * 512 + c] * fc_w[k * 512 + c];
        out[i] = s;
    }
    if (tid == 0) { out[2402] = 0.f; out[2403] = 0.f; }
}

// ===================== host =====================
static float* symaddr(const void* sym) { void* p = nullptr; cudaGetSymbolAddress(&p, sym); return (float*)p; }
static __half* symaddrh(const void* sym) { void* p = nullptr; cudaGetSymbolAddress(&p, sym); return (__half*)p; }

#define GEMM_SMEM2 (3 * 32768)
#define GEMM_SMEM3 (3 * 49152)
#define LOOP_SMEM  (3 * 32768)

extern "C" void kernel_launch(void* const* d_in, const int* in_sizes, int n_in,
                              void* d_out, int out_size)
{
    const float* x      = (const float*)d_in[0];
    const float* wf     = (const float*)d_in[1];
    const float* fc_w   = (const float*)d_in[3];
    const float* fc_b   = (const float*)d_in[4];
    const float* h0_w1  = (const float*)d_in[5];
    const float* h0_bn1 = (const float*)d_in[6];
    const float* h0_w2  = (const float*)d_in[7];
    const float* h0_bn2 = (const float*)d_in[8];
    const float* c0_w1  = (const float*)d_in[9];
    const float* c0_bn1 = (const float*)d_in[10];
    const float* c0_w2  = (const float*)d_in[11];
    const float* c0_bn2 = (const float*)d_in[12];
    const float* mk_w1  = (const float*)d_in[13];
    const float* mk_bn1 = (const float*)d_in[14];
    const float* mk_w2  = (const float*)d_in[15];
    const float* mk_bn2 = (const float*)d_in[16];
    const float* mk_w3  = (const float*)d_in[17];
    const float* lstm_w = (const float*)d_in[18];
    const float* lstm_b = (const float*)d_in[19];
    float* out = (float*)d_out;

    cudaFuncSetAttribute(gemm_mma_k<2>, cudaFuncAttributeMaxDynamicSharedMemorySize, GEMM_SMEM2);
    cudaFuncSetAttribute(gemm_mma_k<3>, cudaFuncAttributeMaxDynamicSharedMemorySize, GEMM_SMEM3);
    cudaFuncSetAttribute(lstm_loop_k, cudaFuncAttributeMaxDynamicSharedMemorySize, LOOP_SMEM);

    float *mx = symaddr(g_mx), *xin = symaddr(g_xin);
    float *y2 = symaddr(g_y2), *mask = symaddr(g_mask);
    float *meanx = symaddr(g_meanx), *mxc = symaddr(g_mxc), *attfea = symaddr(g_attfea);
    float *aw = symaddr(g_aw), *h = symaddr(g_h), *cst = symaddr(g_cst);
    float *gates0 = symaddr(g_gates0), *part = symaddr(g_part), *houts = symaddr(g_houts);
    float *tmphc = symaddr(g_tmphc), *bnc1 = symaddr(g_bnc1);

    __half *axt_h = symaddrh(g_axt_h);
    __half *ay1_h = symaddrh(g_ay1_h);
    __half *sa_h = symaddrh(g_sa_h),   *sa_l = symaddrh(g_sa_l);
    __half *sb_h = symaddrh(g_sb_h),   *sb_l = symaddrh(g_sb_l);
    __half *slh_h = symaddrh(g_slh_h), *slh_l = symaddrh(g_slh_l);
    __half *wmk1_h = symaddrh(g_wmk1_h);
    __half *wmk2_h = symaddrh(g_wmk2_h);
    __half *wgx_h = symaddrh(g_wgx_h);
    __half *whc1_h = symaddrh(g_whc1_h);
    __half *w2h_h = symaddrh(g_w2h_h);
    __half *w2c_h = symaddrh(g_w2c_h);
    __half *wlh_h = symaddrh(g_wlh_h);

    auto blk = [](long long n) { return (unsigned)((n + 255) / 256); };
    dim3 cb(49, 8);
    const long long GCH = 2 * 2048 * PIX;
    const long long HCH = 2 * 512 * PIX;

    // ---- ALL weight repacks in one launch (hi only) ----
    repack_all_k<<<51200, 128>>>(mk_w1, mk_w2, lstm_w, lstm_w, h0_w1, c0_w1, h0_w2, c0_w2,
                                 wmk1_h, wmk2_h, wgx_h, wlh_h,
                                 whc1_h, whc1_h + (size_t)1024 * K18, w2h_h, w2c_h);
    bnconcat_k<<<32, 256>>>(h0_bn1, c0_bn1, bnc1);

    // ---- mask path ----
    im2colx_k<<<blk((long long)2156 * 9 * 1024), 256>>>(x, axt_h);
    {
        dim3 grid(8, 17, 1);
        gemm_mma_k<2><<<grid, 256, GEMM_SMEM2>>>(axt_h, nullptr, wmk1_h, part, K18, K18, 2156, 1024,
                                                 mk_bn1, 2, 0, ay1_h,
                                                 nullptr, nullptr, nullptr, nullptr, 0);
    }
    {
        dim3 grid(4, 17, 2);
        gemm_mma_k<2><<<grid, 256, GEMM_SMEM2>>>(ay1_h, nullptr, wmk2_h, part, K9, K9 / 2, 2156, 512,
                                                 nullptr, 0, (long long)44 * 512 * PIX, nullptr,
                                                 nullptr, nullptr, nullptr, nullptr, 0);
    }
    finish_k<<<blk((long long)44 * 512 * PIX), 256>>>(part, 2, 44 * 512 * PIX, mk_bn2, y2,
                                                      512, 44 * 512 * PIX, 1);
    mask_final_k<<<NBT, cb>>>(y2, mk_w3, mask, out + 246);

    // ---- masked features + attention ----
    mxmxc_k<<<dim3(NBT, 256), cb>>>(x, mask, mx, mxc);
    attfea_k<<<NBT, 256>>>(mxc, wf, attfea);
    aw_k<<<1, 32>>>(attfea, aw, out + 202);
    meanxin_k<<<blk(2 * 2048 * PIX), 256>>>(mx, aw, meanx, xin);

    // ---- xin GEMM + hc1 GEMM merged (z-multiplex) ----
    im2col_k<<<blk((long long)98 * 9 * 1024), 256>>>(xin, 2048, 0, 2048, 98, sa_h, sa_l);
    im2col_k<<<blk((long long)98 * 9 * 1024), 256>>>(meanx, 2048, 0, 2048, 98, sb_h, sb_l);
    {
        dim3 grid(16, 1, 16);
        gemm_mma_k<3><<<grid, 256, GEMM_SMEM3>>>(sa_h, sa_l, wgx_h, part, K18, K18 / 8, 98, 2048,
                                                 nullptr, 0, GCH, nullptr,
                                                 sb_h, sb_l, whc1_h, part + 8 * GCH, 8);
    }
    ginit8_k<<<blk(GCH), 256>>>(part, lstm_b, gates0);
    finish_k<<<blk(GCH), 256>>>(part + 8 * GCH, 8, (int)GCH, bnc1, tmphc, 2048, (int)GCH, 1);

    // ---- hc2: both branches in ONE launch ----
    im2col_k<<<blk((long long)98 * 9 * 512), 256>>>(tmphc, 2048, 0, 1024, 98, sa_h, sa_l);
    im2col_k<<<blk((long long)98 * 9 * 512), 256>>>(tmphc, 2048, 1024, 1024, 98, sb_h, sb_l);
    {
        dim3 grid(4, 1, 8);
        gemm_mma_k<3><<<grid, 256, GEMM_SMEM3>>>(sa_h, sa_l, w2h_h, part, K9, K9 / 4, 98, 512,
                                                 nullptr, 0, HCH, nullptr,
                                                 sb_h, sb_l, w2c_h, part + 4 * HCH, 4);
    }
    finish_k<<<blk(HCH), 256>>>(part, 4, (int)HCH, h0_bn2, h, 512, (int)HCH, 1);
    finish_k<<<blk(HCH), 256>>>(part + 4 * HCH, 4, (int)HCH, c0_bn2, cst, 512, (int)HCH, 1);

    // ---- seed im2col for h0 (hi only), then recurrence in ONE persistent kernel ----
    im2col_k<<<blk((long long)98 * 9 * 256), 256>>>(h, 512, 0, 512, 98, slh_h, nullptr);
    zerobar_k<<<1, 1>>>();
    lstm_loop_k<<<128, 256, LOOP_SMEM>>>(slh_h, wlh_h, part, gates0, cst, houts);

    final_k<<<1, 512>>>(houts, fc_w, fc_b, out);
}